// round 2
// baseline (speedup 1.0000x reference)
#include <cuda_runtime.h>
#include <cstdint>

// Problem constants
#define BB 8
#define NN 2048
#define DD 768
#define TRIPLE 2304   // 3*768

// Scratch (device globals; no allocations anywhere)
__device__ float g_qkv[(size_t)BB * NN * TRIPLE];   // 151 MB, stored tf32-rounded
__device__ float g_scores[(size_t)BB * NN * NN];    // 134 MB
__device__ float g_xc[(size_t)BB * NN * DD];        // 48 MB, x pre-converted to tf32
__device__ float g_wc[(size_t)DD * TRIPLE];         // 6.8 MB, W pre-converted to tf32

__device__ __forceinline__ uint32_t f2tf32(float x) {
    uint32_t r;
    asm("cvt.rna.tf32.f32 %0, %1;" : "=r"(r) : "f"(x));
    return r;
}
__device__ __forceinline__ float f2tf32f(float x) {
    return __uint_as_float(f2tf32(x));
}

__device__ __forceinline__ void mma_tf32(float c[4], const uint32_t a[4], const uint32_t b[2]) {
    asm volatile(
        "mma.sync.aligned.m16n8k8.row.col.f32.tf32.tf32.f32 "
        "{%0,%1,%2,%3}, {%4,%5,%6,%7}, {%8,%9}, {%0,%1,%2,%3};"
        : "+f"(c[0]), "+f"(c[1]), "+f"(c[2]), "+f"(c[3])
        : "r"(a[0]), "r"(a[1]), "r"(a[2]), "r"(a[3]), "r"(b[0]), "r"(b[1]));
}

__device__ __forceinline__ void cp16(float* dst_smem, const float* src) {
    uint32_t d = (uint32_t)__cvta_generic_to_shared(dst_smem);
    asm volatile("cp.async.cg.shared.global [%0], [%1], 16;" :: "r"(d), "l"(src));
}
#define CP_COMMIT() asm volatile("cp.async.commit_group;")
#define CP_WAIT(n)  asm volatile("cp.async.wait_group %0;" :: "n"(n))

// Elementwise fp32 -> tf32-rounded (stored as fp32 bit pattern)
__global__ void cvt_tf32_kernel(const float4* __restrict__ in, float4* __restrict__ out, int n4)
{
    int i = blockIdx.x * blockDim.x + threadIdx.x;
    if (i < n4) {
        float4 v = in[i];
        v.x = f2tf32f(v.x); v.y = f2tf32f(v.y);
        v.z = f2tf32f(v.z); v.w = f2tf32f(v.w);
        out[i] = v;
    }
}

// TF32 tensor-core GEMM, cp.async double-buffered.
//   C[M,N] = A[M,K] * B (+bias) (*scale)
//   BT=false: B row-major [K,N], ldb; tile stored k-major [32][136]
//   BT=true : B row-major [N,K], ldb (C = A*B^T); tile stored n-major [128][36]
// Inputs must already be tf32-rounded. CTA tile 128x128, BK=32, 256 threads.
// All dims are exact tile multiples -> no bounds checks.
template<bool BT, bool BIAS, bool SCALE, bool CVTOUT>
__global__ __launch_bounds__(256)
void gemm_tf32_kernel(const float* __restrict__ A, int lda, long long sA,
                      const float* __restrict__ B, int ldb, long long sB,
                      float* __restrict__ C, int ldc, long long sC,
                      int K, const float* __restrict__ bias, float scale)
{
    constexpr int ALD   = 36;                 // banks (lr*4+lc) distinct
    constexpr int BROWS = BT ? 128 : 32;
    constexpr int BLD   = BT ? 36 : 136;      // 136: banks (lc*8+lr) distinct

    extern __shared__ float sm[];
    float* As = sm;                           // [2][128][36]
    float* Bs = sm + 2 * 128 * ALD;           // [2][BROWS][BLD]

    const int t  = threadIdx.x;
    const int bm = blockIdx.y * 128;
    const int bn = blockIdx.x * 128;
    const float* Ap = A + (long long)blockIdx.z * sA + (long long)bm * lda;
    const float* Bp = B + (long long)blockIdx.z * sB
                        + (BT ? (long long)bn * ldb : (long long)bn);
    C += (long long)blockIdx.z * sC;

    const int warp = t >> 5, lane = t & 31;
    const int wm = (warp & 1) * 64;
    const int wn = (warp >> 1) * 32;
    const int lr = lane >> 2, lc = lane & 3;

    float acc[4][4][4];
#pragma unroll
    for (int i = 0; i < 4; i++)
#pragma unroll
        for (int j = 0; j < 4; j++)
#pragma unroll
            for (int r = 0; r < 4; r++) acc[i][j][r] = 0.f;

    const int a_row = t >> 3;          // 0..31 (+i*32)
    const int a_col = (t & 7) * 4;     // 0..28
    const int b_row = t >> 5;          // 0..7  (+i*8)   [!BT]
    const int b_col = (t & 31) * 4;    // 0..124         [!BT]

    auto load_tiles = [&](int k0, int buf) {
        float* ad = As + buf * 128 * ALD;
#pragma unroll
        for (int i = 0; i < 4; i++) {
            const int r = a_row + i * 32;
            cp16(ad + r * ALD + a_col, Ap + (long long)r * lda + k0 + a_col);
        }
        float* bd = Bs + buf * BROWS * BLD;
        if (BT) {
#pragma unroll
            for (int i = 0; i < 4; i++) {
                const int n = a_row + i * 32;
                cp16(bd + n * BLD + a_col, Bp + (long long)n * ldb + k0 + a_col);
            }
        } else {
#pragma unroll
            for (int i = 0; i < 4; i++) {
                const int r = b_row + i * 8;
                cp16(bd + r * BLD + b_col, Bp + (long long)(k0 + r) * ldb + b_col);
            }
        }
    };

    const int ntiles = K / 32;
    int buf = 0;
    load_tiles(0, 0);
    CP_COMMIT();

    for (int it = 0; it < ntiles; ++it) {
        if (it + 1 < ntiles) {
            load_tiles((it + 1) * 32, buf ^ 1);
            CP_COMMIT();
            CP_WAIT(1);
        } else {
            CP_WAIT(0);
        }
        __syncthreads();

        const float* Ab = As + buf * 128 * ALD;
        const float* Bb = Bs + buf * BROWS * BLD;
#pragma unroll
        for (int ks = 0; ks < 4; ks++) {
            const int kk = ks * 8;
            uint32_t af[4][4];
#pragma unroll
            for (int mt = 0; mt < 4; mt++) {
                const float* ap = Ab + (wm + mt * 16 + lr) * ALD + kk + lc;
                af[mt][0] = __float_as_uint(ap[0]);
                af[mt][1] = __float_as_uint(ap[8 * ALD]);
                af[mt][2] = __float_as_uint(ap[4]);
                af[mt][3] = __float_as_uint(ap[8 * ALD + 4]);
            }
            uint32_t bf[4][2];
#pragma unroll
            for (int nt = 0; nt < 4; nt++) {
                const int n0 = wn + nt * 8 + lr;
                if (BT) {
                    const float* bp = Bb + n0 * BLD + kk + lc;
                    bf[nt][0] = __float_as_uint(bp[0]);
                    bf[nt][1] = __float_as_uint(bp[4]);
                } else {
                    bf[nt][0] = __float_as_uint(Bb[(kk + lc) * BLD + n0]);
                    bf[nt][1] = __float_as_uint(Bb[(kk + 4 + lc) * BLD + n0]);
                }
            }
#pragma unroll
            for (int mt = 0; mt < 4; mt++)
#pragma unroll
                for (int nt = 0; nt < 4; nt++)
                    mma_tf32(acc[mt][nt], af[mt], bf[nt]);
        }
        __syncthreads();
        buf ^= 1;
    }

    // ---- epilogue ----
#pragma unroll
    for (int mt = 0; mt < 4; mt++) {
#pragma unroll
        for (int nt = 0; nt < 4; nt++) {
            const int r   = bm + wm + mt * 16 + lr;
            const int col = bn + wn + nt * 8 + lc * 2;
            float v0 = acc[mt][nt][0], v1 = acc[mt][nt][1];
            float v2 = acc[mt][nt][2], v3 = acc[mt][nt][3];
            if (BIAS) {
                const float bi0 = bias[col], bi1 = bias[col + 1];
                v0 += bi0; v1 += bi1; v2 += bi0; v3 += bi1;
            }
            if (SCALE) { v0 *= scale; v1 *= scale; v2 *= scale; v3 *= scale; }
            if (CVTOUT) {
                v0 = f2tf32f(v0); v1 = f2tf32f(v1);
                v2 = f2tf32f(v2); v3 = f2tf32f(v3);
            }
            *reinterpret_cast<float2*>(&C[(long long)r * ldc + col]) = make_float2(v0, v1);
            *reinterpret_cast<float2*>(&C[(long long)(r + 8) * ldc + col]) = make_float2(v2, v3);
        }
    }
}

// Row softmax over S (B*N rows of N=2048), in place; output tf32-rounded.
__global__ __launch_bounds__(256)
void softmax_kernel(float* __restrict__ S)
{
    const long long row = blockIdx.x;
    float* p = S + row * (long long)NN;
    const int t = threadIdx.x;

    float v[8];
    float mx = -1e30f;
#pragma unroll
    for (int i = 0; i < 8; i++) {
        v[i] = p[t + i * 256];
        mx = fmaxf(mx, v[i]);
    }
#pragma unroll
    for (int o = 16; o > 0; o >>= 1)
        mx = fmaxf(mx, __shfl_xor_sync(0xFFFFFFFFu, mx, o));

    __shared__ float redm[8];
    __shared__ float reds[8];
    if ((t & 31) == 0) redm[t >> 5] = mx;
    __syncthreads();
#pragma unroll
    for (int i = 0; i < 8; i++) mx = fmaxf(mx, redm[i]);

    float s = 0.f;
#pragma unroll
    for (int i = 0; i < 8; i++) {
        v[i] = __expf(v[i] - mx);
        s += v[i];
    }
#pragma unroll
    for (int o = 16; o > 0; o >>= 1)
        s += __shfl_xor_sync(0xFFFFFFFFu, s, o);
    if ((t & 31) == 0) reds[t >> 5] = s;
    __syncthreads();
    s = 0.f;
#pragma unroll
    for (int i = 0; i < 8; i++) s += reds[i];

    const float inv = 1.f / s;
#pragma unroll
    for (int i = 0; i < 8; i++)
        p[t + i * 256] = f2tf32f(v[i] * inv);
}

extern "C" void kernel_launch(void* const* d_in, const int* in_sizes, int n_in,
                              void* d_out, int out_size)
{
    const float* x    = (const float*)d_in[0];   // [8, 2048, 768]
    const float* W    = (const float*)d_in[1];   // [768, 2304]
    const float* bias = (const float*)d_in[2];   // [2304]
    float* out        = (float*)d_out;           // [8, 2048, 768]

    float *qkv, *sc, *xc, *wc;
    cudaGetSymbolAddress((void**)&qkv, g_qkv);
    cudaGetSymbolAddress((void**)&sc,  g_scores);
    cudaGetSymbolAddress((void**)&xc,  g_xc);
    cudaGetSymbolAddress((void**)&wc,  g_wc);

    // Dynamic smem sizes per instantiation
    const int SM_BT  = (2 * 128 * 36 + 2 * 128 * 36) * 4;  // 73728
    const int SM_BN  = (2 * 128 * 36 + 2 * 32 * 136) * 4;  // 71680
    cudaFuncSetAttribute(gemm_tf32_kernel<false, true,  false, true >,
                         cudaFuncAttributeMaxDynamicSharedMemorySize, SM_BN);
    cudaFuncSetAttribute(gemm_tf32_kernel<true,  false, true,  false>,
                         cudaFuncAttributeMaxDynamicSharedMemorySize, SM_BT);
    cudaFuncSetAttribute(gemm_tf32_kernel<false, false, false, false>,
                         cudaFuncAttributeMaxDynamicSharedMemorySize, SM_BN);

    const float scale = 0.03608439182435161f;    // 1/sqrt(768)

    // 0) pre-convert x and W to tf32-rounded
    {
        int n4x = (BB * NN * DD) / 4;
        int n4w = (DD * TRIPLE) / 4;
        cvt_tf32_kernel<<<(n4x + 255) / 256, 256>>>((const float4*)x, (float4*)xc, n4x);
        cvt_tf32_kernel<<<(n4w + 255) / 256, 256>>>((const float4*)W, (float4*)wc, n4w);
    }

    // 1) qkv = xc @ wc + b : M=16384, N=2304, K=768 (stores tf32-rounded)
    gemm_tf32_kernel<false, true, false, true>
        <<<dim3(TRIPLE / 128, (BB * NN) / 128, 1), 256, SM_BN>>>(
        xc, DD, 0,
        wc, TRIPLE, 0,
        qkv, TRIPLE, 0,
        DD, bias, 1.f);

    // 2) S = Q @ K^T * scale : per batch M=2048, N=2048, K=768
    gemm_tf32_kernel<true, false, true, false>
        <<<dim3(NN / 128, NN / 128, BB), 256, SM_BT>>>(
        qkv,      TRIPLE, (long long)NN * TRIPLE,
        qkv + DD, TRIPLE, (long long)NN * TRIPLE,
        sc,       NN,     (long long)NN * NN,
        DD, nullptr, scale);

    // 3) softmax rows (stores tf32-rounded P)
    softmax_kernel<<<BB * NN, 256>>>(sc);

    // 4) C = P @ V : per batch M=2048, N=768, K=2048
    gemm_tf32_kernel<false, false, false, false>
        <<<dim3(DD / 128, NN / 128, BB), 256, SM_BN>>>(
        sc,           NN,     (long long)NN * NN,
        qkv + 2 * DD, TRIPLE, (long long)NN * TRIPLE,
        out,          DD,     (long long)NN * DD,
        NN, nullptr, 1.f);
}

// round 3
// speedup vs baseline: 1.0748x; 1.0748x over previous
#include <cuda_runtime.h>
#include <cstdint>

// Problem constants
#define BB 8
#define NN 2048
#define DD 768
#define TRIPLE 2304   // 3*768

// Scratch (device globals; no allocations anywhere)
__device__ float g_qkv[(size_t)BB * NN * TRIPLE];   // 151 MB, stored tf32-rounded
__device__ float g_scores[(size_t)BB * NN * NN];    // 134 MB
__device__ float g_xc[(size_t)BB * NN * DD];        // 48 MB, x pre-converted to tf32
__device__ float g_wc[(size_t)DD * TRIPLE];         // 6.8 MB, W pre-converted to tf32

__device__ __forceinline__ uint32_t f2tf32(float x) {
    uint32_t r;
    asm("cvt.rna.tf32.f32 %0, %1;" : "=r"(r) : "f"(x));
    return r;
}
__device__ __forceinline__ float f2tf32f(float x) {
    return __uint_as_float(f2tf32(x));
}

__device__ __forceinline__ void mma_tf32(float c[4], const uint32_t a[4], const uint32_t b[2]) {
    asm volatile(
        "mma.sync.aligned.m16n8k8.row.col.f32.tf32.tf32.f32 "
        "{%0,%1,%2,%3}, {%4,%5,%6,%7}, {%8,%9}, {%0,%1,%2,%3};"
        : "+f"(c[0]), "+f"(c[1]), "+f"(c[2]), "+f"(c[3])
        : "r"(a[0]), "r"(a[1]), "r"(a[2]), "r"(a[3]), "r"(b[0]), "r"(b[1]));
}

__device__ __forceinline__ void cp16(float* dst_smem, const float* src) {
    uint32_t d = (uint32_t)__cvta_generic_to_shared(dst_smem);
    asm volatile("cp.async.cg.shared.global [%0], [%1], 16;" :: "r"(d), "l"(src));
}
#define CP_COMMIT() asm volatile("cp.async.commit_group;")
#define CP_WAIT(n)  asm volatile("cp.async.wait_group %0;" :: "n"(n))

// Elementwise fp32 -> tf32-rounded
__global__ void cvt_tf32_kernel(const float4* __restrict__ in, float4* __restrict__ out, int n4)
{
    int i = blockIdx.x * blockDim.x + threadIdx.x;
    if (i < n4) {
        float4 v = in[i];
        v.x = f2tf32f(v.x); v.y = f2tf32f(v.y);
        v.z = f2tf32f(v.z); v.w = f2tf32f(v.w);
        out[i] = v;
    }
}

// TF32 tensor-core GEMM, cp.async double-buffered.
//   C[M,N] = A[M,K] * B (+bias) (*scale)
//   BT=false: B row-major [K,N], ldb; tile k-major [32][264]
//   BT=true : B row-major [N,K], ldb (C = A*B^T); tile n-major [256][36]
// CTA tile 128x256, BK=32, 256 threads = 8 warps of 64x64.
// Inputs must already be tf32-rounded. All dims exact tile multiples.
template<bool BT, bool BIAS, bool SCALE, bool CVTOUT>
__global__ __launch_bounds__(256, 1)
void gemm_tf32_kernel(const float* __restrict__ A, int lda, long long sA,
                      const float* __restrict__ B, int ldb, long long sB,
                      float* __restrict__ C, int ldc, long long sC,
                      int K, const float* __restrict__ bias, float scale)
{
    constexpr int ALD   = 36;
    constexpr int BROWS = BT ? 256 : 32;
    constexpr int BLD   = BT ? 36 : 264;

    extern __shared__ float sm[];
    float* As = sm;                     // [2][128][36]
    float* Bs = sm + 2 * 128 * ALD;     // [2][BROWS][BLD]

    const int t  = threadIdx.x;
    const int bm = blockIdx.y * 128;
    const int bn = blockIdx.x * 256;
    const float* Ap = A + (long long)blockIdx.z * sA + (long long)bm * lda;
    const float* Bp = B + (long long)blockIdx.z * sB
                        + (BT ? (long long)bn * ldb : (long long)bn);
    C += (long long)blockIdx.z * sC;

    const int warp = t >> 5, lane = t & 31;
    const int wm = (warp & 1) * 64;     // 2 warp rows
    const int wn = (warp >> 1) * 64;    // 4 warp cols
    const int lr = lane >> 2, lc = lane & 3;

    float acc[4][8][4];
#pragma unroll
    for (int i = 0; i < 4; i++)
#pragma unroll
        for (int j = 0; j < 8; j++)
#pragma unroll
            for (int r = 0; r < 4; r++) acc[i][j][r] = 0.f;

    const int a_row = t >> 3;          // 0..31 (+i*32)
    const int a_col = (t & 7) * 4;     // 0..28

    auto load_tiles = [&](int k0, int buf) {
        float* ad = As + buf * 128 * ALD;
#pragma unroll
        for (int i = 0; i < 4; i++) {
            const int r = a_row + i * 32;
            cp16(ad + r * ALD + a_col, Ap + (long long)r * lda + k0 + a_col);
        }
        float* bd = Bs + buf * BROWS * BLD;
        if (BT) {
#pragma unroll
            for (int i = 0; i < 8; i++) {
                const int n = a_row + i * 32;
                cp16(bd + n * BLD + a_col, Bp + (long long)n * ldb + k0 + a_col);
            }
        } else {
            const int br = t >> 5;          // 0..7 (+i*8)
            const int bc = (t & 31) * 8;    // 0..248
#pragma unroll
            for (int i = 0; i < 4; i++) {
                const int r = br + i * 8;
                cp16(bd + r * BLD + bc,     Bp + (long long)(k0 + r) * ldb + bc);
                cp16(bd + r * BLD + bc + 4, Bp + (long long)(k0 + r) * ldb + bc + 4);
            }
        }
    };

    const int ntiles = K / 32;
    int buf = 0;
    load_tiles(0, 0);
    CP_COMMIT();

    for (int it = 0; it < ntiles; ++it) {
        if (it + 1 < ntiles) {
            load_tiles((it + 1) * 32, buf ^ 1);
            CP_COMMIT();
            CP_WAIT(1);
        } else {
            CP_WAIT(0);
        }
        __syncthreads();

        const float* Ab = As + buf * 128 * ALD;
        const float* Bb = Bs + buf * BROWS * BLD;
#pragma unroll
        for (int ks = 0; ks < 4; ks++) {
            const int kk = ks * 8;
            uint32_t af[4][4];
#pragma unroll
            for (int mt = 0; mt < 4; mt++) {
                const float* ap = Ab + (wm + mt * 16 + lr) * ALD + kk + lc;
                af[mt][0] = __float_as_uint(ap[0]);
                af[mt][1] = __float_as_uint(ap[8 * ALD]);
                af[mt][2] = __float_as_uint(ap[4]);
                af[mt][3] = __float_as_uint(ap[8 * ALD + 4]);
            }
            uint32_t bf[8][2];
#pragma unroll
            for (int nt = 0; nt < 8; nt++) {
                const int n0 = wn + nt * 8 + lr;
                if (BT) {
                    const float* bp = Bb + n0 * BLD + kk + lc;
                    bf[nt][0] = __float_as_uint(bp[0]);
                    bf[nt][1] = __float_as_uint(bp[4]);
                } else {
                    bf[nt][0] = __float_as_uint(Bb[(kk + lc) * BLD + n0]);
                    bf[nt][1] = __float_as_uint(Bb[(kk + 4 + lc) * BLD + n0]);
                }
            }
#pragma unroll
            for (int mt = 0; mt < 4; mt++)
#pragma unroll
                for (int nt = 0; nt < 8; nt++)
                    mma_tf32(acc[mt][nt], af[mt], bf[nt]);
        }
        __syncthreads();
        buf ^= 1;
    }

    // ---- epilogue ----
#pragma unroll
    for (int mt = 0; mt < 4; mt++) {
#pragma unroll
        for (int nt = 0; nt < 8; nt++) {
            const int r   = bm + wm + mt * 16 + lr;
            const int col = bn + wn + nt * 8 + lc * 2;
            float v0 = acc[mt][nt][0], v1 = acc[mt][nt][1];
            float v2 = acc[mt][nt][2], v3 = acc[mt][nt][3];
            if (BIAS) {
                const float bi0 = bias[col], bi1 = bias[col + 1];
                v0 += bi0; v1 += bi1; v2 += bi0; v3 += bi1;
            }
            if (SCALE) { v0 *= scale; v1 *= scale; v2 *= scale; v3 *= scale; }
            if (CVTOUT) {
                v0 = f2tf32f(v0); v1 = f2tf32f(v1);
                v2 = f2tf32f(v2); v3 = f2tf32f(v3);
            }
            *reinterpret_cast<float2*>(&C[(long long)r * ldc + col]) = make_float2(v0, v1);
            *reinterpret_cast<float2*>(&C[(long long)(r + 8) * ldc + col]) = make_float2(v2, v3);
        }
    }
}

// Row softmax over S (B*N rows of N=2048), in place; output tf32-rounded.
__global__ __launch_bounds__(256)
void softmax_kernel(float* __restrict__ S)
{
    const long long row = blockIdx.x;
    float* p = S + row * (long long)NN;
    const int t = threadIdx.x;

    float v[8];
    float mx = -1e30f;
#pragma unroll
    for (int i = 0; i < 8; i++) {
        v[i] = p[t + i * 256];
        mx = fmaxf(mx, v[i]);
    }
#pragma unroll
    for (int o = 16; o > 0; o >>= 1)
        mx = fmaxf(mx, __shfl_xor_sync(0xFFFFFFFFu, mx, o));

    __shared__ float redm[8];
    __shared__ float reds[8];
    if ((t & 31) == 0) redm[t >> 5] = mx;
    __syncthreads();
#pragma unroll
    for (int i = 0; i < 8; i++) mx = fmaxf(mx, redm[i]);

    float s = 0.f;
#pragma unroll
    for (int i = 0; i < 8; i++) {
        v[i] = __expf(v[i] - mx);
        s += v[i];
    }
#pragma unroll
    for (int o = 16; o > 0; o >>= 1)
        s += __shfl_xor_sync(0xFFFFFFFFu, s, o);
    if ((t & 31) == 0) reds[t >> 5] = s;
    __syncthreads();
    s = 0.f;
#pragma unroll
    for (int i = 0; i < 8; i++) s += reds[i];

    const float inv = 1.f / s;
#pragma unroll
    for (int i = 0; i < 8; i++)
        p[t + i * 256] = f2tf32f(v[i] * inv);
}

extern "C" void kernel_launch(void* const* d_in, const int* in_sizes, int n_in,
                              void* d_out, int out_size)
{
    const float* x    = (const float*)d_in[0];   // [8, 2048, 768]
    const float* W    = (const float*)d_in[1];   // [768, 2304]
    const float* bias = (const float*)d_in[2];   // [2304]
    float* out        = (float*)d_out;           // [8, 2048, 768]

    float *qkv, *sc, *xc, *wc;
    cudaGetSymbolAddress((void**)&qkv, g_qkv);
    cudaGetSymbolAddress((void**)&sc,  g_scores);
    cudaGetSymbolAddress((void**)&xc,  g_xc);
    cudaGetSymbolAddress((void**)&wc,  g_wc);

    // Dynamic smem per instantiation
    const int SM_BT = (2 * 128 * 36 + 2 * 256 * 36) * 4;   // 110592
    const int SM_BN = (2 * 128 * 36 + 2 * 32 * 264) * 4;   // 104448
    cudaFuncSetAttribute(gemm_tf32_kernel<false, true,  false, true >,
                         cudaFuncAttributeMaxDynamicSharedMemorySize, SM_BN);
    cudaFuncSetAttribute(gemm_tf32_kernel<true,  false, true,  false>,
                         cudaFuncAttributeMaxDynamicSharedMemorySize, SM_BT);
    cudaFuncSetAttribute(gemm_tf32_kernel<false, false, false, false>,
                         cudaFuncAttributeMaxDynamicSharedMemorySize, SM_BN);

    const float scale = 0.03608439182435161f;    // 1/sqrt(768)

    // 0) pre-convert x and W to tf32-rounded
    {
        int n4x = (BB * NN * DD) / 4;
        int n4w = (DD * TRIPLE) / 4;
        cvt_tf32_kernel<<<(n4x + 255) / 256, 256>>>((const float4*)x, (float4*)xc, n4x);
        cvt_tf32_kernel<<<(n4w + 255) / 256, 256>>>((const float4*)W, (float4*)wc, n4w);
    }

    // 1) qkv = xc @ wc + b : M=16384, N=2304, K=768 (stores tf32-rounded)
    gemm_tf32_kernel<false, true, false, true>
        <<<dim3(TRIPLE / 256, (BB * NN) / 128, 1), 256, SM_BN>>>(
        xc, DD, 0,
        wc, TRIPLE, 0,
        qkv, TRIPLE, 0,
        DD, bias, 1.f);

    // 2) S = Q @ K^T * scale : per batch M=2048, N=2048, K=768
    gemm_tf32_kernel<true, false, true, false>
        <<<dim3(NN / 256, NN / 128, BB), 256, SM_BT>>>(
        qkv,      TRIPLE, (long long)NN * TRIPLE,
        qkv + DD, TRIPLE, (long long)NN * TRIPLE,
        sc,       NN,     (long long)NN * NN,
        DD, nullptr, scale);

    // 3) softmax rows (stores tf32-rounded P)
    softmax_kernel<<<BB * NN, 256>>>(sc);

    // 4) C = P @ V : per batch M=2048, N=768, K=2048
    gemm_tf32_kernel<false, false, false, false>
        <<<dim3(DD / 256, NN / 128, BB), 256, SM_BN>>>(
        sc,           NN,     (long long)NN * NN,
        qkv + 2 * DD, TRIPLE, (long long)NN * TRIPLE,
        out,          DD,     (long long)NN * DD,
        NN, nullptr, 1.f);
}

// round 6
// speedup vs baseline: 1.1509x; 1.0708x over previous
#include <cuda_runtime.h>
#include <cstdint>

// Problem constants
#define BB 8
#define NN 2048
#define DD 768
#define TRIPLE 2304   // 3*768

// Scratch (device globals; no allocations anywhere)
__device__ float g_qkv[(size_t)BB * NN * TRIPLE];   // 151 MB, stored tf32-rounded
__device__ float g_scores[(size_t)BB * NN * NN];    // 134 MB
__device__ float g_xc[(size_t)BB * NN * DD];        // 48 MB, x pre-converted to tf32
__device__ float g_wc[(size_t)DD * TRIPLE];         // 6.8 MB, W pre-converted to tf32

__device__ __forceinline__ uint32_t f2tf32(float x) {
    uint32_t r;
    asm("cvt.rna.tf32.f32 %0, %1;" : "=r"(r) : "f"(x));
    return r;
}
__device__ __forceinline__ float f2tf32f(float x) {
    return __uint_as_float(f2tf32(x));
}

__device__ __forceinline__ void mma_tf32(float c[4], const uint32_t a[4], const uint32_t b[2]) {
    asm volatile(
        "mma.sync.aligned.m16n8k8.row.col.f32.tf32.tf32.f32 "
        "{%0,%1,%2,%3}, {%4,%5,%6,%7}, {%8,%9}, {%0,%1,%2,%3};"
        : "+f"(c[0]), "+f"(c[1]), "+f"(c[2]), "+f"(c[3])
        : "r"(a[0]), "r"(a[1]), "r"(a[2]), "r"(a[3]), "r"(b[0]), "r"(b[1]));
}

__device__ __forceinline__ void cp16(float* dst_smem, const float* src) {
    uint32_t d = (uint32_t)__cvta_generic_to_shared(dst_smem);
    asm volatile("cp.async.cg.shared.global [%0], [%1], 16;" :: "r"(d), "l"(src));
}
#define CP_COMMIT() asm volatile("cp.async.commit_group;")
#define CP_WAIT(n)  asm volatile("cp.async.wait_group %0;" :: "n"(n))

// Elementwise fp32 -> tf32-rounded (stored as fp32 bit pattern)
__global__ void cvt_tf32_kernel(const float4* __restrict__ in, float4* __restrict__ out, int n4)
{
    int i = blockIdx.x * blockDim.x + threadIdx.x;
    if (i < n4) {
        float4 v = in[i];
        v.x = f2tf32f(v.x); v.y = f2tf32f(v.y);
        v.z = f2tf32f(v.z); v.w = f2tf32f(v.w);
        out[i] = v;
    }
}

// TF32 tensor-core GEMM, cp.async double-buffered, 2 CTAs/SM.
//   C[M,N] = A[M,K] * B (+bias) (*scale)
//   BT=false: B row-major [K,N], ldb; tile stored k-major [32][136]
//   BT=true : B row-major [N,K], ldb (C = A*B^T); tile n-major [128][36]
// Inputs must already be tf32-rounded. CTA tile 128x128, BK=32, 256 threads
// = 8 warps of 64x32. All dims are exact tile multiples -> no bounds checks.
template<bool BT, bool BIAS, bool SCALE, bool CVTOUT>
__global__ __launch_bounds__(256, 2)
void gemm_tf32_kernel(const float* __restrict__ A, int lda, long long sA,
                      const float* __restrict__ B, int ldb, long long sB,
                      float* __restrict__ C, int ldc, long long sC,
                      int K, const float* __restrict__ bias, float scale)
{
    constexpr int ALD   = 36;                 // banks (lr*4+lc) distinct
    constexpr int BROWS = BT ? 128 : 32;
    constexpr int BLD   = BT ? 36 : 136;      // 136: banks (lc*8+lr) distinct

    extern __shared__ float sm[];
    float* As = sm;                           // [2][128][36]
    float* Bs = sm + 2 * 128 * ALD;           // [2][BROWS][BLD]

    const int t  = threadIdx.x;
    const int bm = blockIdx.y * 128;
    const int bn = blockIdx.x * 128;
    const float* Ap = A + (long long)blockIdx.z * sA + (long long)bm * lda;
    const float* Bp = B + (long long)blockIdx.z * sB
                        + (BT ? (long long)bn * ldb : (long long)bn);
    C += (long long)blockIdx.z * sC;

    const int warp = t >> 5, lane = t & 31;
    const int wm = (warp & 1) * 64;
    const int wn = (warp >> 1) * 32;
    const int lr = lane >> 2, lc = lane & 3;

    float acc[4][4][4];
#pragma unroll
    for (int i = 0; i < 4; i++)
#pragma unroll
        for (int j = 0; j < 4; j++)
#pragma unroll
            for (int r = 0; r < 4; r++) acc[i][j][r] = 0.f;

    const int a_row = t >> 3;          // 0..31 (+i*32)
    const int a_col = (t & 7) * 4;     // 0..28
    const int b_row = t >> 5;          // 0..7  (+i*8)   [!BT]
    const int b_col = (t & 31) * 4;    // 0..124         [!BT]

    auto load_tiles = [&](int k0, int buf) {
        float* ad = As + buf * 128 * ALD;
#pragma unroll
        for (int i = 0; i < 4; i++) {
            const int r = a_row + i * 32;
            cp16(ad + r * ALD + a_col, Ap + (long long)r * lda + k0 + a_col);
        }
        float* bd = Bs + buf * BROWS * BLD;
        if (BT) {
#pragma unroll
            for (int i = 0; i < 4; i++) {
                const int n = a_row + i * 32;
                cp16(bd + n * BLD + a_col, Bp + (long long)n * ldb + k0 + a_col);
            }
        } else {
#pragma unroll
            for (int i = 0; i < 4; i++) {
                const int r = b_row + i * 8;
                cp16(bd + r * BLD + b_col, Bp + (long long)(k0 + r) * ldb + b_col);
            }
        }
    };

    const int ntiles = K / 32;
    int buf = 0;
    load_tiles(0, 0);
    CP_COMMIT();

    for (int it = 0; it < ntiles; ++it) {
        if (it + 1 < ntiles) {
            load_tiles((it + 1) * 32, buf ^ 1);
            CP_COMMIT();
            CP_WAIT(1);
        } else {
            CP_WAIT(0);
        }
        __syncthreads();

        const float* Ab = As + buf * 128 * ALD;
        const float* Bb = Bs + buf * BROWS * BLD;
#pragma unroll
        for (int ks = 0; ks < 4; ks++) {
            const int kk = ks * 8;
            uint32_t af[4][4];
#pragma unroll
            for (int mt = 0; mt < 4; mt++) {
                const float* ap = Ab + (wm + mt * 16 + lr) * ALD + kk + lc;
                af[mt][0] = __float_as_uint(ap[0]);
                af[mt][1] = __float_as_uint(ap[8 * ALD]);
                af[mt][2] = __float_as_uint(ap[4]);
                af[mt][3] = __float_as_uint(ap[8 * ALD + 4]);
            }
            uint32_t bf[4][2];
#pragma unroll
            for (int nt = 0; nt < 4; nt++) {
                const int n0 = wn + nt * 8 + lr;
                if (BT) {
                    const float* bp = Bb + n0 * BLD + kk + lc;
                    bf[nt][0] = __float_as_uint(bp[0]);
                    bf[nt][1] = __float_as_uint(bp[4]);
                } else {
                    bf[nt][0] = __float_as_uint(Bb[(kk + lc) * BLD + n0]);
                    bf[nt][1] = __float_as_uint(Bb[(kk + 4 + lc) * BLD + n0]);
                }
            }
#pragma unroll
            for (int mt = 0; mt < 4; mt++)
#pragma unroll
                for (int nt = 0; nt < 4; nt++)
                    mma_tf32(acc[mt][nt], af[mt], bf[nt]);
        }
        __syncthreads();
        buf ^= 1;
    }

    // ---- epilogue ----
#pragma unroll
    for (int mt = 0; mt < 4; mt++) {
#pragma unroll
        for (int nt = 0; nt < 4; nt++) {
            const int r   = bm + wm + mt * 16 + lr;
            const int col = bn + wn + nt * 8 + lc * 2;
            float v0 = acc[mt][nt][0], v1 = acc[mt][nt][1];
            float v2 = acc[mt][nt][2], v3 = acc[mt][nt][3];
            if (BIAS) {
                const float bi0 = bias[col], bi1 = bias[col + 1];
                v0 += bi0; v1 += bi1; v2 += bi0; v3 += bi1;
            }
            if (SCALE) { v0 *= scale; v1 *= scale; v2 *= scale; v3 *= scale; }
            if (CVTOUT) {
                v0 = f2tf32f(v0); v1 = f2tf32f(v1);
                v2 = f2tf32f(v2); v3 = f2tf32f(v3);
            }
            *reinterpret_cast<float2*>(&C[(long long)r * ldc + col]) = make_float2(v0, v1);
            *reinterpret_cast<float2*>(&C[(long long)(r + 8) * ldc + col]) = make_float2(v2, v3);
        }
    }
}

// Row softmax over S (B*N rows of N=2048), in place; output tf32-rounded.
__global__ __launch_bounds__(256)
void softmax_kernel(float* __restrict__ S)
{
    const long long row = blockIdx.x;
    float* p = S + row * (long long)NN;
    const int t = threadIdx.x;

    float v[8];
    float mx = -1e30f;
#pragma unroll
    for (int i = 0; i < 8; i++) {
        v[i] = p[t + i * 256];
        mx = fmaxf(mx, v[i]);
    }
#pragma unroll
    for (int o = 16; o > 0; o >>= 1)
        mx = fmaxf(mx, __shfl_xor_sync(0xFFFFFFFFu, mx, o));

    __shared__ float redm[8];
    __shared__ float reds[8];
    if ((t & 31) == 0) redm[t >> 5] = mx;
    __syncthreads();
#pragma unroll
    for (int i = 0; i < 8; i++) mx = fmaxf(mx, redm[i]);

    float s = 0.f;
#pragma unroll
    for (int i = 0; i < 8; i++) {
        v[i] = __expf(v[i] - mx);
        s += v[i];
    }
#pragma unroll
    for (int o = 16; o > 0; o >>= 1)
        s += __shfl_xor_sync(0xFFFFFFFFu, s, o);
    if ((t & 31) == 0) reds[t >> 5] = s;
    __syncthreads();
    s = 0.f;
#pragma unroll
    for (int i = 0; i < 8; i++) s += reds[i];

    const float inv = 1.f / s;
#pragma unroll
    for (int i = 0; i < 8; i++)
        p[t + i * 256] = f2tf32f(v[i] * inv);
}

extern "C" void kernel_launch(void* const* d_in, const int* in_sizes, int n_in,
                              void* d_out, int out_size)
{
    const float* x    = (const float*)d_in[0];   // [8, 2048, 768]
    const float* W    = (const float*)d_in[1];   // [768, 2304]
    const float* bias = (const float*)d_in[2];   // [2304]
    float* out        = (float*)d_out;           // [8, 2048, 768]

    float *qkv, *sc, *xc, *wc;
    cudaGetSymbolAddress((void**)&qkv, g_qkv);
    cudaGetSymbolAddress((void**)&sc,  g_scores);
    cudaGetSymbolAddress((void**)&xc,  g_xc);
    cudaGetSymbolAddress((void**)&wc,  g_wc);

    // Dynamic smem per instantiation (<=48KB would be automatic, but set anyway)
    const int SM_BT  = (2 * 128 * 36 + 2 * 128 * 36) * 4;  // 73728
    const int SM_BN  = (2 * 128 * 36 + 2 * 32 * 136) * 4;  // 71680
    cudaFuncSetAttribute(gemm_tf32_kernel<false, true,  false, true >,
                         cudaFuncAttributeMaxDynamicSharedMemorySize, SM_BN);
    cudaFuncSetAttribute(gemm_tf32_kernel<true,  false, true,  false>,
                         cudaFuncAttributeMaxDynamicSharedMemorySize, SM_BT);
    cudaFuncSetAttribute(gemm_tf32_kernel<false, false, false, false>,
                         cudaFuncAttributeMaxDynamicSharedMemorySize, SM_BN);

    const float scale = 0.03608439182435161f;    // 1/sqrt(768)

    // 0) pre-convert x and W to tf32-rounded
    {
        int n4x = (BB * NN * DD) / 4;
        int n4w = (DD * TRIPLE) / 4;
        cvt_tf32_kernel<<<(n4x + 255) / 256, 256>>>((const float4*)x, (float4*)xc, n4x);
        cvt_tf32_kernel<<<(n4w + 255) / 256, 256>>>((const float4*)W, (float4*)wc, n4w);
    }

    // 1) qkv = xc @ wc + b : M=16384, N=2304, K=768 (stores tf32-rounded)
    gemm_tf32_kernel<false, true, false, true>
        <<<dim3(TRIPLE / 128, (BB * NN) / 128, 1), 256, SM_BN>>>(
        xc, DD, 0,
        wc, TRIPLE, 0,
        qkv, TRIPLE, 0,
        DD, bias, 1.f);

    // 2) S = Q @ K^T * scale : per batch M=2048, N=2048, K=768
    gemm_tf32_kernel<true, false, true, false>
        <<<dim3(NN / 128, NN / 128, BB), 256, SM_BT>>>(
        qkv,      TRIPLE, (long long)NN * TRIPLE,
        qkv + DD, TRIPLE, (long long)NN * TRIPLE,
        sc,       NN,     (long long)NN * NN,
        DD, nullptr, scale);

    // 3) softmax rows (stores tf32-rounded P)
    softmax_kernel<<<BB * NN, 256>>>(sc);

    // 4) C = P @ V : per batch M=2048, N=768, K=2048
    gemm_tf32_kernel<false, false, false, false>
        <<<dim3(DD / 128, NN / 128, BB), 256, SM_BN>>>(
        sc,           NN,     (long long)NN * NN,
        qkv + 2 * DD, TRIPLE, (long long)NN * TRIPLE,
        out,          DD,     (long long)NN * DD,
        NN, nullptr, 1.f);
}

// round 7
// speedup vs baseline: 2.0326x; 1.7661x over previous
#include <cuda_runtime.h>
#include <cuda_fp16.h>
#include <cstdint>

// Problem constants
#define BB 8
#define NN 2048
#define DD 768
#define TRIPLE 2304   // 3*768

// Scratch (device globals; no allocations anywhere)
__device__ __half g_qkv[(size_t)BB * NN * TRIPLE];  // 75 MB fp16 (q,k,v interleaved)
__device__ float  g_scores[(size_t)BB * NN * NN];   // 134 MB fp32
__device__ __half g_p[(size_t)BB * NN * NN];        // 67 MB fp16 softmax probs
__device__ __half g_xh[(size_t)BB * NN * DD];       // 25 MB x in fp16
__device__ __half g_wh[(size_t)DD * TRIPLE];        // 3.5 MB W in fp16

// ---------------- helpers ----------------
__device__ __forceinline__ void mma_f16(float c[4], const uint32_t a[4], const uint32_t b[2]) {
    asm volatile(
        "mma.sync.aligned.m16n8k16.row.col.f32.f16.f16.f32 "
        "{%0,%1,%2,%3}, {%4,%5,%6,%7}, {%8,%9}, {%0,%1,%2,%3};"
        : "+f"(c[0]), "+f"(c[1]), "+f"(c[2]), "+f"(c[3])
        : "r"(a[0]), "r"(a[1]), "r"(a[2]), "r"(a[3]), "r"(b[0]), "r"(b[1]));
}

__device__ __forceinline__ void ldsm4(uint32_t& r0, uint32_t& r1, uint32_t& r2, uint32_t& r3,
                                      uint32_t addr) {
    asm volatile("ldmatrix.sync.aligned.m8n8.x4.shared.b16 {%0,%1,%2,%3}, [%4];"
                 : "=r"(r0), "=r"(r1), "=r"(r2), "=r"(r3) : "r"(addr));
}
__device__ __forceinline__ void ldsm4t(uint32_t& r0, uint32_t& r1, uint32_t& r2, uint32_t& r3,
                                       uint32_t addr) {
    asm volatile("ldmatrix.sync.aligned.m8n8.x4.trans.shared.b16 {%0,%1,%2,%3}, [%4];"
                 : "=r"(r0), "=r"(r1), "=r"(r2), "=r"(r3) : "r"(addr));
}

__device__ __forceinline__ void cp16(const __half* dst_smem, const __half* src) {
    uint32_t d = (uint32_t)__cvta_generic_to_shared(dst_smem);
    asm volatile("cp.async.cg.shared.global [%0], [%1], 16;" :: "r"(d), "l"(src));
}
#define CP_COMMIT() asm volatile("cp.async.commit_group;")
#define CP_WAIT(n)  asm volatile("cp.async.wait_group %0;" :: "n"(n))

// fp32 -> fp16 conversion (vectorized)
__global__ void cvt_f16_kernel(const float4* __restrict__ in, uint2* __restrict__ out, int n4)
{
    int i = blockIdx.x * blockDim.x + threadIdx.x;
    if (i < n4) {
        float4 v = in[i];
        __half2 lo = __floats2half2_rn(v.x, v.y);
        __half2 hi = __floats2half2_rn(v.z, v.w);
        out[i] = make_uint2(*(uint32_t*)&lo, *(uint32_t*)&hi);
    }
}

// ---------------- FP16 tensor-core GEMM ----------------
//   C[M,N] = A[M,K](f16) * B(f16) (+bias) (*scale), accum fp32
//   BT=true : B row-major [N,K] (C = A*B^T); smem tile n-major [128][40]
//   BT=false: B row-major [K,N]; smem tile k-major [32][136], read via ldmatrix.trans
// CTA tile 128x128, BK=32, 256 thr = 8 warps of 64x32, 2 CTAs/SM, cp.async x2 buf.
// All dims exact tile multiples -> no bounds checks.
template<bool BT, bool BIAS, bool SCALE, bool HALFOUT>
__global__ __launch_bounds__(256, 2)
void gemm_f16_kernel(const __half* __restrict__ A, int lda, long long sA,
                     const __half* __restrict__ B, int ldb, long long sB,
                     float* __restrict__ Cf, int ldc, long long sC,
                     int K, const float* __restrict__ bias, float scale)
{
    constexpr int ALD   = 40;                 // halves; 80B stride: 5r%8 distinct
    constexpr int BROWS = BT ? 128 : 32;
    constexpr int BLD   = BT ? 40 : 136;      // 272B stride: 17r%8 distinct

    extern __shared__ __half sm[];
    __half* As = sm;                          // [2][128][40]
    __half* Bs = sm + 2 * 128 * ALD;          // [2][BROWS][BLD]

    const int t  = threadIdx.x;
    const int bm = blockIdx.y * 128;
    const int bn = blockIdx.x * 128;
    const __half* Ap = A + (long long)blockIdx.z * sA + (long long)bm * lda;
    const __half* Bp = B + (long long)blockIdx.z * sB
                         + (BT ? (long long)bn * ldb : (long long)bn);
    float*  Cp = Cf + (long long)blockIdx.z * sC;
    __half* Ch = reinterpret_cast<__half*>(Cf) + (long long)blockIdx.z * sC;

    const int warp = t >> 5, lane = t & 31;
    const int wm = (warp & 1) * 64;
    const int wn = (warp >> 1) * 32;
    const int lr = lane >> 2, lc = lane & 3;

    float acc[4][4][4];
#pragma unroll
    for (int i = 0; i < 4; i++)
#pragma unroll
        for (int j = 0; j < 4; j++)
#pragma unroll
            for (int r = 0; r < 4; r++) acc[i][j][r] = 0.f;

    // cp.async mappings (16B = 8 halves)
    const int a_row = t >> 2;           // 0..63 (+64)
    const int a_c8  = (t & 3) * 8;      // 0,8,16,24

    auto load_tiles = [&](int k0, int buf) {
        __half* ad = As + buf * 128 * ALD;
#pragma unroll
        for (int i = 0; i < 2; i++) {
            const int r = a_row + i * 64;
            cp16(ad + r * ALD + a_c8, Ap + (long long)r * lda + k0 + a_c8);
        }
        __half* bd = Bs + buf * BROWS * BLD;
        if (BT) {
#pragma unroll
            for (int i = 0; i < 2; i++) {
                const int n = a_row + i * 64;
                cp16(bd + n * BLD + a_c8, Bp + (long long)n * ldb + k0 + a_c8);
            }
        } else {
            const int br = t >> 4;            // 0..15 (+16)
            const int bc = (t & 15) * 8;      // 0..120
#pragma unroll
            for (int i = 0; i < 2; i++) {
                const int r = br + i * 16;
                cp16(bd + r * BLD + bc, Bp + (long long)(k0 + r) * ldb + bc);
            }
        }
    };

    // ldmatrix per-lane address components
    const int a_lr = lane & 15;             // matrix row
    const int a_lk = (lane >> 4) << 3;      // k-half select
    const int bt_n = (lane & 7) + ((lane >> 4) & 1) * 8;   // BT: n within 16-group
    const int bt_k = ((lane >> 3) & 1) * 8;                // BT: k-half
    const int bn_k = (lane & 7) + ((lane >> 3) & 1) * 8;   // !BT: k row
    const int bn_n = ((lane >> 4) & 1) * 8;                // !BT: n-half

    const int ntiles = K / 32;
    int buf = 0;
    load_tiles(0, 0);
    CP_COMMIT();

    for (int it = 0; it < ntiles; ++it) {
        if (it + 1 < ntiles) {
            load_tiles((it + 1) * 32, buf ^ 1);
            CP_COMMIT();
            CP_WAIT(1);
        } else {
            CP_WAIT(0);
        }
        __syncthreads();

        const __half* Ab = As + buf * 128 * ALD;
        const __half* Bb = Bs + buf * BROWS * BLD;
#pragma unroll
        for (int ks = 0; ks < 2; ks++) {
            const int kk = ks * 16;
            uint32_t af[4][4];
#pragma unroll
            for (int mt = 0; mt < 4; mt++) {
                const __half* p = Ab + (wm + mt * 16 + a_lr) * ALD + kk + a_lk;
                ldsm4(af[mt][0], af[mt][1], af[mt][2], af[mt][3],
                      (uint32_t)__cvta_generic_to_shared(p));
            }
            uint32_t bf[4][2];
#pragma unroll
            for (int np = 0; np < 2; np++) {   // nt pair: nt = 2np, 2np+1
                if (BT) {
                    const __half* p = Bb + (wn + np * 16 + bt_n) * BLD + kk + bt_k;
                    ldsm4(bf[np * 2][0], bf[np * 2][1], bf[np * 2 + 1][0], bf[np * 2 + 1][1],
                          (uint32_t)__cvta_generic_to_shared(p));
                } else {
                    const __half* p = Bb + (kk + bn_k) * BLD + wn + np * 16 + bn_n;
                    ldsm4t(bf[np * 2][0], bf[np * 2][1], bf[np * 2 + 1][0], bf[np * 2 + 1][1],
                           (uint32_t)__cvta_generic_to_shared(p));
                }
            }
#pragma unroll
            for (int mt = 0; mt < 4; mt++)
#pragma unroll
                for (int nt = 0; nt < 4; nt++)
                    mma_f16(acc[mt][nt], af[mt], bf[nt]);
        }
        __syncthreads();
        buf ^= 1;
    }

    // ---- epilogue ----
#pragma unroll
    for (int mt = 0; mt < 4; mt++) {
#pragma unroll
        for (int nt = 0; nt < 4; nt++) {
            const int r   = bm + wm + mt * 16 + lr;
            const int col = bn + wn + nt * 8 + lc * 2;
            float v0 = acc[mt][nt][0], v1 = acc[mt][nt][1];
            float v2 = acc[mt][nt][2], v3 = acc[mt][nt][3];
            if (BIAS) {
                const float bi0 = bias[col], bi1 = bias[col + 1];
                v0 += bi0; v1 += bi1; v2 += bi0; v3 += bi1;
            }
            if (SCALE) { v0 *= scale; v1 *= scale; v2 *= scale; v3 *= scale; }
            if (HALFOUT) {
                __half2 h01 = __floats2half2_rn(v0, v1);
                __half2 h23 = __floats2half2_rn(v2, v3);
                *reinterpret_cast<__half2*>(&Ch[(long long)r * ldc + col])       = h01;
                *reinterpret_cast<__half2*>(&Ch[(long long)(r + 8) * ldc + col]) = h23;
            } else {
                *reinterpret_cast<float2*>(&Cp[(long long)r * ldc + col])       = make_float2(v0, v1);
                *reinterpret_cast<float2*>(&Cp[(long long)(r + 8) * ldc + col]) = make_float2(v2, v3);
            }
        }
    }
}

// Row softmax: read fp32 S, write fp16 P.
__global__ __launch_bounds__(256)
void softmax_kernel(const float* __restrict__ S, __half* __restrict__ P)
{
    const long long row = blockIdx.x;
    const float* p = S + row * (long long)NN;
    __half* po = P + row * (long long)NN;
    const int t = threadIdx.x;

    float v[8];
    float mx = -1e30f;
#pragma unroll
    for (int i = 0; i < 8; i++) {
        v[i] = p[t + i * 256];
        mx = fmaxf(mx, v[i]);
    }
#pragma unroll
    for (int o = 16; o > 0; o >>= 1)
        mx = fmaxf(mx, __shfl_xor_sync(0xFFFFFFFFu, mx, o));

    __shared__ float redm[8];
    __shared__ float reds[8];
    if ((t & 31) == 0) redm[t >> 5] = mx;
    __syncthreads();
#pragma unroll
    for (int i = 0; i < 8; i++) mx = fmaxf(mx, redm[i]);

    float s = 0.f;
#pragma unroll
    for (int i = 0; i < 8; i++) {
        v[i] = __expf(v[i] - mx);
        s += v[i];
    }
#pragma unroll
    for (int o = 16; o > 0; o >>= 1)
        s += __shfl_xor_sync(0xFFFFFFFFu, s, o);
    if ((t & 31) == 0) reds[t >> 5] = s;
    __syncthreads();
    s = 0.f;
#pragma unroll
    for (int i = 0; i < 8; i++) s += reds[i];

    const float inv = 1.f / s;
#pragma unroll
    for (int i = 0; i < 8; i++)
        po[t + i * 256] = __float2half(v[i] * inv);
}

// ---------------- host ----------------
extern "C" void kernel_launch(void* const* d_in, const int* in_sizes, int n_in,
                              void* d_out, int out_size)
{
    const float* x    = (const float*)d_in[0];   // [8, 2048, 768]
    const float* W    = (const float*)d_in[1];   // [768, 2304]
    const float* bias = (const float*)d_in[2];   // [2304]
    float* out        = (float*)d_out;           // [8, 2048, 768]

    __half *qkv, *ph, *xh, *wh; float *sc;
    cudaGetSymbolAddress((void**)&qkv, g_qkv);
    cudaGetSymbolAddress((void**)&sc,  g_scores);
    cudaGetSymbolAddress((void**)&ph,  g_p);
    cudaGetSymbolAddress((void**)&xh,  g_xh);
    cudaGetSymbolAddress((void**)&wh,  g_wh);

    // Dynamic smem (halves): BT: 2*(128*40 + 128*40)*2 = 40960 B ; !BT: 2*(128*40 + 32*136)*2 = 37888 B
    const int SM_BT = 2 * (128 * 40 + 128 * 40) * 2;
    const int SM_BN = 2 * (128 * 40 + 32 * 136) * 2;

    const float scale = 0.03608439182435161f;    // 1/sqrt(768)

    // 0) x, W -> fp16
    {
        int n4x = (BB * NN * DD) / 4;
        int n4w = (DD * TRIPLE) / 4;
        cvt_f16_kernel<<<(n4x + 255) / 256, 256>>>((const float4*)x, (uint2*)xh, n4x);
        cvt_f16_kernel<<<(n4w + 255) / 256, 256>>>((const float4*)W, (uint2*)wh, n4w);
    }

    // 1) qkv = xh @ wh + b : M=16384, N=2304, K=768 -> fp16 out
    gemm_f16_kernel<false, true, false, true>
        <<<dim3(TRIPLE / 128, (BB * NN) / 128, 1), 256, SM_BN>>>(
        xh, DD, 0,
        wh, TRIPLE, 0,
        (float*)qkv, TRIPLE, 0,
        DD, bias, 1.f);

    // 2) S = Q @ K^T * scale : per batch M=2048, N=2048, K=768 -> fp32 scores
    gemm_f16_kernel<true, false, true, false>
        <<<dim3(NN / 128, NN / 128, BB), 256, SM_BT>>>(
        qkv,      TRIPLE, (long long)NN * TRIPLE,
        qkv + DD, TRIPLE, (long long)NN * TRIPLE,
        sc,       NN,     (long long)NN * NN,
        DD, nullptr, scale);

    // 3) softmax rows -> fp16 P
    softmax_kernel<<<BB * NN, 256>>>(sc, ph);

    // 4) out = P @ V : per batch M=2048, N=768, K=2048 -> fp32 out
    gemm_f16_kernel<false, false, false, false>
        <<<dim3(DD / 128, NN / 128, BB), 256, SM_BN>>>(
        ph,           NN,     (long long)NN * NN,
        qkv + 2 * DD, TRIPLE, (long long)NN * TRIPLE,
        out,          DD,     (long long)NN * DD,
        NN, nullptr, 1.f);
}

// round 8
// speedup vs baseline: 2.1676x; 1.0664x over previous
#include <cuda_runtime.h>
#include <cuda_fp16.h>
#include <cstdint>

// Problem constants
#define BB 8
#define NN 2048
#define DD 768
#define TRIPLE 2304   // 3*768

// Scratch (device globals; no allocations anywhere)
__device__ __half g_qkv[(size_t)BB * NN * TRIPLE];  // 75 MB fp16 (q,k,v interleaved)
__device__ float  g_scores[(size_t)BB * NN * NN];   // 134 MB fp32
__device__ __half g_p[(size_t)BB * NN * NN];        // 67 MB fp16 softmax probs
__device__ __half g_xh[(size_t)BB * NN * DD];       // 25 MB x in fp16
__device__ __half g_wh[(size_t)DD * TRIPLE];        // 3.5 MB W in fp16

// ---------------- helpers ----------------
__device__ __forceinline__ void mma_f16(float c[4], const uint32_t a[4], const uint32_t b[2]) {
    asm volatile(
        "mma.sync.aligned.m16n8k16.row.col.f32.f16.f16.f32 "
        "{%0,%1,%2,%3}, {%4,%5,%6,%7}, {%8,%9}, {%0,%1,%2,%3};"
        : "+f"(c[0]), "+f"(c[1]), "+f"(c[2]), "+f"(c[3])
        : "r"(a[0]), "r"(a[1]), "r"(a[2]), "r"(a[3]), "r"(b[0]), "r"(b[1]));
}

__device__ __forceinline__ void ldsm4(uint32_t& r0, uint32_t& r1, uint32_t& r2, uint32_t& r3,
                                      uint32_t addr) {
    asm volatile("ldmatrix.sync.aligned.m8n8.x4.shared.b16 {%0,%1,%2,%3}, [%4];"
                 : "=r"(r0), "=r"(r1), "=r"(r2), "=r"(r3) : "r"(addr));
}
__device__ __forceinline__ void ldsm4t(uint32_t& r0, uint32_t& r1, uint32_t& r2, uint32_t& r3,
                                       uint32_t addr) {
    asm volatile("ldmatrix.sync.aligned.m8n8.x4.trans.shared.b16 {%0,%1,%2,%3}, [%4];"
                 : "=r"(r0), "=r"(r1), "=r"(r2), "=r"(r3) : "r"(addr));
}

__device__ __forceinline__ void cp16(const __half* dst_smem, const __half* src) {
    uint32_t d = (uint32_t)__cvta_generic_to_shared(dst_smem);
    asm volatile("cp.async.cg.shared.global [%0], [%1], 16;" :: "r"(d), "l"(src));
}
#define CP_COMMIT() asm volatile("cp.async.commit_group;")
#define CP_WAIT(n)  asm volatile("cp.async.wait_group %0;" :: "n"(n))

// fp32 -> fp16 conversion (vectorized)
__global__ void cvt_f16_kernel(const float4* __restrict__ in, uint2* __restrict__ out, int n4)
{
    int i = blockIdx.x * blockDim.x + threadIdx.x;
    if (i < n4) {
        float4 v = in[i];
        __half2 lo = __floats2half2_rn(v.x, v.y);
        __half2 hi = __floats2half2_rn(v.z, v.w);
        out[i] = make_uint2(*(uint32_t*)&lo, *(uint32_t*)&hi);
    }
}

// ---------------- FP16 tensor-core GEMM ----------------
//   C[M,N] = A[M,K](f16) * B(f16) (+bias) (*scale), accum fp32
//   BT=true : B row-major [N,K] (C = A*B^T); smem tile n-major [128][72]
//   BT=false: B row-major [K,N]; smem tile k-major [64][136], read via ldmatrix.trans
// CTA tile 128x128, BK=64, 256 thr = 8 warps of 64x32, 2 CTAs/SM, 3-stage cp.async.
// All dims exact tile multiples -> no bounds checks.
template<bool BT, bool BIAS, bool SCALE, bool HALFOUT>
__global__ __launch_bounds__(256, 2)
void gemm_f16_kernel(const __half* __restrict__ A, int lda, long long sA,
                     const __half* __restrict__ B, int ldb, long long sB,
                     float* __restrict__ Cf, int ldc, long long sC,
                     int K, const float* __restrict__ bias, float scale)
{
    constexpr int ALD   = 72;                 // 144B row stride = 9x16B (odd) -> conflict-free
    constexpr int BROWS = BT ? 128 : 64;
    constexpr int BLD   = BT ? 72 : 136;      // 136: 272B = 17x16B (odd)
    constexpr int ASTG  = 128 * ALD;          // halves per A stage
    constexpr int BSTG  = BROWS * BLD;

    extern __shared__ __half sm[];
    __half* As = sm;                          // [3][128][72]
    __half* Bs = sm + 3 * ASTG;               // [3][BROWS][BLD]

    const int t  = threadIdx.x;
    const int bm = blockIdx.y * 128;
    const int bn = blockIdx.x * 128;
    const __half* Ap = A + (long long)blockIdx.z * sA + (long long)bm * lda;
    const __half* Bp = B + (long long)blockIdx.z * sB
                         + (BT ? (long long)bn * ldb : (long long)bn);
    float*  Cp = Cf + (long long)blockIdx.z * sC;
    __half* Ch = reinterpret_cast<__half*>(Cf) + (long long)blockIdx.z * sC;

    const int warp = t >> 5, lane = t & 31;
    const int wm = (warp & 1) * 64;
    const int wn = (warp >> 1) * 32;
    const int lr = lane >> 2, lc = lane & 3;

    float acc[4][4][4];
#pragma unroll
    for (int i = 0; i < 4; i++)
#pragma unroll
        for (int j = 0; j < 4; j++)
#pragma unroll
            for (int r = 0; r < 4; r++) acc[i][j][r] = 0.f;

    auto load_tiles = [&](int k0, int buf) {
        __half* ad = As + buf * ASTG;
        // A: 128 rows x 64 cols = 1024 x 16B chunks
#pragma unroll
        for (int i = 0; i < 4; i++) {
            const int idx = t + i * 256;          // 0..1023
            const int r = idx >> 3, c8 = (idx & 7) * 8;
            cp16(ad + r * ALD + c8, Ap + (long long)r * lda + k0 + c8);
        }
        __half* bd = Bs + buf * BSTG;
        if (BT) {
#pragma unroll
            for (int i = 0; i < 4; i++) {
                const int idx = t + i * 256;
                const int n = idx >> 3, c8 = (idx & 7) * 8;
                cp16(bd + n * BLD + c8, Bp + (long long)n * ldb + k0 + c8);
            }
        } else {
            // B: 64 rows x 128 cols = 1024 x 16B chunks
#pragma unroll
            for (int i = 0; i < 4; i++) {
                const int idx = t + i * 256;
                const int r = idx >> 4, c8 = (idx & 15) * 8;
                cp16(bd + r * BLD + c8, Bp + (long long)(k0 + r) * ldb + c8);
            }
        }
    };

    // ldmatrix per-lane address components
    const int a_lr = lane & 15;             // matrix row
    const int a_lk = (lane >> 4) << 3;      // k-half select
    const int bt_n = (lane & 7) + ((lane >> 4) & 1) * 8;   // BT: n within 16-group
    const int bt_k = ((lane >> 3) & 1) * 8;                // BT: k-half
    const int bn_k = (lane & 7) + ((lane >> 3) & 1) * 8;   // !BT: k row
    const int bn_n = ((lane >> 4) & 1) * 8;                // !BT: n-half

    const int ntiles = K / 64;              // >= 2 always here
    load_tiles(0, 0);  CP_COMMIT();
    load_tiles(64, 1); CP_COMMIT();

    for (int it = 0; it < ntiles; ++it) {
        if (it + 2 < ntiles) {
            load_tiles((it + 2) * 64, (it + 2) % 3);
            CP_COMMIT();
            CP_WAIT(2);
        } else if (it + 1 < ntiles) {
            CP_WAIT(1);
        } else {
            CP_WAIT(0);
        }
        __syncthreads();

        const int buf = it % 3;
        const __half* Ab = As + buf * ASTG;
        const __half* Bb = Bs + buf * BSTG;
#pragma unroll
        for (int ks = 0; ks < 4; ks++) {
            const int kk = ks * 16;
            uint32_t af[4][4];
#pragma unroll
            for (int mt = 0; mt < 4; mt++) {
                const __half* p = Ab + (wm + mt * 16 + a_lr) * ALD + kk + a_lk;
                ldsm4(af[mt][0], af[mt][1], af[mt][2], af[mt][3],
                      (uint32_t)__cvta_generic_to_shared(p));
            }
            uint32_t bf[4][2];
#pragma unroll
            for (int np = 0; np < 2; np++) {   // nt pair: nt = 2np, 2np+1
                if (BT) {
                    const __half* p = Bb + (wn + np * 16 + bt_n) * BLD + kk + bt_k;
                    ldsm4(bf[np * 2][0], bf[np * 2][1], bf[np * 2 + 1][0], bf[np * 2 + 1][1],
                          (uint32_t)__cvta_generic_to_shared(p));
                } else {
                    const __half* p = Bb + (kk + bn_k) * BLD + wn + np * 16 + bn_n;
                    ldsm4t(bf[np * 2][0], bf[np * 2][1], bf[np * 2 + 1][0], bf[np * 2 + 1][1],
                           (uint32_t)__cvta_generic_to_shared(p));
                }
            }
#pragma unroll
            for (int mt = 0; mt < 4; mt++)
#pragma unroll
                for (int nt = 0; nt < 4; nt++)
                    mma_f16(acc[mt][nt], af[mt], bf[nt]);
        }
        __syncthreads();
    }

    // ---- epilogue ----
#pragma unroll
    for (int mt = 0; mt < 4; mt++) {
#pragma unroll
        for (int nt = 0; nt < 4; nt++) {
            const int r   = bm + wm + mt * 16 + lr;
            const int col = bn + wn + nt * 8 + lc * 2;
            float v0 = acc[mt][nt][0], v1 = acc[mt][nt][1];
            float v2 = acc[mt][nt][2], v3 = acc[mt][nt][3];
            if (BIAS) {
                const float bi0 = bias[col], bi1 = bias[col + 1];
                v0 += bi0; v1 += bi1; v2 += bi0; v3 += bi1;
            }
            if (SCALE) { v0 *= scale; v1 *= scale; v2 *= scale; v3 *= scale; }
            if (HALFOUT) {
                __half2 h01 = __floats2half2_rn(v0, v1);
                __half2 h23 = __floats2half2_rn(v2, v3);
                *reinterpret_cast<__half2*>(&Ch[(long long)r * ldc + col])       = h01;
                *reinterpret_cast<__half2*>(&Ch[(long long)(r + 8) * ldc + col]) = h23;
            } else {
                *reinterpret_cast<float2*>(&Cp[(long long)r * ldc + col])       = make_float2(v0, v1);
                *reinterpret_cast<float2*>(&Cp[(long long)(r + 8) * ldc + col]) = make_float2(v2, v3);
            }
        }
    }
}

// Row softmax: read fp32 S, write fp16 P.
__global__ __launch_bounds__(256)
void softmax_kernel(const float* __restrict__ S, __half* __restrict__ P)
{
    const long long row = blockIdx.x;
    const float* p = S + row * (long long)NN;
    __half* po = P + row * (long long)NN;
    const int t = threadIdx.x;

    float v[8];
    float mx = -1e30f;
#pragma unroll
    for (int i = 0; i < 8; i++) {
        v[i] = p[t + i * 256];
        mx = fmaxf(mx, v[i]);
    }
#pragma unroll
    for (int o = 16; o > 0; o >>= 1)
        mx = fmaxf(mx, __shfl_xor_sync(0xFFFFFFFFu, mx, o));

    __shared__ float redm[8];
    __shared__ float reds[8];
    if ((t & 31) == 0) redm[t >> 5] = mx;
    __syncthreads();
#pragma unroll
    for (int i = 0; i < 8; i++) mx = fmaxf(mx, redm[i]);

    float s = 0.f;
#pragma unroll
    for (int i = 0; i < 8; i++) {
        v[i] = __expf(v[i] - mx);
        s += v[i];
    }
#pragma unroll
    for (int o = 16; o > 0; o >>= 1)
        s += __shfl_xor_sync(0xFFFFFFFFu, s, o);
    if ((t & 31) == 0) reds[t >> 5] = s;
    __syncthreads();
    s = 0.f;
#pragma unroll
    for (int i = 0; i < 8; i++) s += reds[i];

    const float inv = 1.f / s;
#pragma unroll
    for (int i = 0; i < 8; i++)
        po[t + i * 256] = __float2half(v[i] * inv);
}

// ---------------- host ----------------
extern "C" void kernel_launch(void* const* d_in, const int* in_sizes, int n_in,
                              void* d_out, int out_size)
{
    const float* x    = (const float*)d_in[0];   // [8, 2048, 768]
    const float* W    = (const float*)d_in[1];   // [768, 2304]
    const float* bias = (const float*)d_in[2];   // [2304]
    float* out        = (float*)d_out;           // [8, 2048, 768]

    __half *qkv, *ph, *xh, *wh; float *sc;
    cudaGetSymbolAddress((void**)&qkv, g_qkv);
    cudaGetSymbolAddress((void**)&sc,  g_scores);
    cudaGetSymbolAddress((void**)&ph,  g_p);
    cudaGetSymbolAddress((void**)&xh,  g_xh);
    cudaGetSymbolAddress((void**)&wh,  g_wh);

    // Dynamic smem (bytes): BT: 3*(128*72 + 128*72)*2 = 110592 ; !BT: 3*(128*72 + 64*136)*2 = 107520
    const int SM_BT = 3 * (128 * 72 + 128 * 72) * 2;
    const int SM_BN = 3 * (128 * 72 + 64 * 136) * 2;
    cudaFuncSetAttribute(gemm_f16_kernel<false, true,  false, true >,
                         cudaFuncAttributeMaxDynamicSharedMemorySize, SM_BN);
    cudaFuncSetAttribute(gemm_f16_kernel<true,  false, true,  false>,
                         cudaFuncAttributeMaxDynamicSharedMemorySize, SM_BT);
    cudaFuncSetAttribute(gemm_f16_kernel<false, false, false, false>,
                         cudaFuncAttributeMaxDynamicSharedMemorySize, SM_BN);

    const float scale = 0.03608439182435161f;    // 1/sqrt(768)

    // 0) x, W -> fp16
    {
        int n4x = (BB * NN * DD) / 4;
        int n4w = (DD * TRIPLE) / 4;
        cvt_f16_kernel<<<(n4x + 255) / 256, 256>>>((const float4*)x, (uint2*)xh, n4x);
        cvt_f16_kernel<<<(n4w + 255) / 256, 256>>>((const float4*)W, (uint2*)wh, n4w);
    }

    // 1) qkv = xh @ wh + b : M=16384, N=2304, K=768 -> fp16 out
    gemm_f16_kernel<false, true, false, true>
        <<<dim3(TRIPLE / 128, (BB * NN) / 128, 1), 256, SM_BN>>>(
        xh, DD, 0,
        wh, TRIPLE, 0,
        (float*)qkv, TRIPLE, 0,
        DD, bias, 1.f);

    // 2) S = Q @ K^T * scale : per batch M=2048, N=2048, K=768 -> fp32 scores
    gemm_f16_kernel<true, false, true, false>
        <<<dim3(NN / 128, NN / 128, BB), 256, SM_BT>>>(
        qkv,      TRIPLE, (long long)NN * TRIPLE,
        qkv + DD, TRIPLE, (long long)NN * TRIPLE,
        sc,       NN,     (long long)NN * NN,
        DD, nullptr, scale);

    // 3) softmax rows -> fp16 P
    softmax_kernel<<<BB * NN, 256>>>(sc, ph);

    // 4) out = P @ V : per batch M=2048, N=768, K=2048 -> fp32 out
    gemm_f16_kernel<false, false, false, false>
        <<<dim3(DD / 128, NN / 128, BB), 256, SM_BN>>>(
        ph,           NN,     (long long)NN * NN,
        qkv + 2 * DD, TRIPLE, (long long)NN * TRIPLE,
        out,          DD,     (long long)NN * DD,
        NN, nullptr, 1.f);
}

// round 9
// speedup vs baseline: 2.1915x; 1.0110x over previous
#include <cuda_runtime.h>
#include <cuda_fp16.h>
#include <cstdint>

// Problem constants
#define BB 8
#define NN 2048
#define DD 768
#define TRIPLE 2304   // 3*768

// Scratch (device globals; no allocations anywhere)
__device__ __half g_qkv[(size_t)BB * NN * TRIPLE];  // 75 MB fp16 (q,k,v interleaved)
__device__ float  g_scores[(size_t)BB * NN * NN];   // 134 MB fp32
__device__ __half g_p[(size_t)BB * NN * NN];        // 67 MB fp16 softmax probs
__device__ __half g_xh[(size_t)BB * NN * DD];       // 25 MB x in fp16
__device__ __half g_wh[(size_t)DD * TRIPLE];        // 3.5 MB W in fp16

// ---------------- helpers ----------------
__device__ __forceinline__ void mma_f16(float c[4], const uint32_t a[4], const uint32_t b[2]) {
    asm volatile(
        "mma.sync.aligned.m16n8k16.row.col.f32.f16.f16.f32 "
        "{%0,%1,%2,%3}, {%4,%5,%6,%7}, {%8,%9}, {%0,%1,%2,%3};"
        : "+f"(c[0]), "+f"(c[1]), "+f"(c[2]), "+f"(c[3])
        : "r"(a[0]), "r"(a[1]), "r"(a[2]), "r"(a[3]), "r"(b[0]), "r"(b[1]));
}

__device__ __forceinline__ void ldsm4(uint32_t& r0, uint32_t& r1, uint32_t& r2, uint32_t& r3,
                                      uint32_t addr) {
    asm volatile("ldmatrix.sync.aligned.m8n8.x4.shared.b16 {%0,%1,%2,%3}, [%4];"
                 : "=r"(r0), "=r"(r1), "=r"(r2), "=r"(r3) : "r"(addr));
}
__device__ __forceinline__ void ldsm4t(uint32_t& r0, uint32_t& r1, uint32_t& r2, uint32_t& r3,
                                       uint32_t addr) {
    asm volatile("ldmatrix.sync.aligned.m8n8.x4.trans.shared.b16 {%0,%1,%2,%3}, [%4];"
                 : "=r"(r0), "=r"(r1), "=r"(r2), "=r"(r3) : "r"(addr));
}

__device__ __forceinline__ void cp16(const __half* dst_smem, const __half* src) {
    uint32_t d = (uint32_t)__cvta_generic_to_shared(dst_smem);
    asm volatile("cp.async.cg.shared.global [%0], [%1], 16;" :: "r"(d), "l"(src));
}
#define CP_COMMIT() asm volatile("cp.async.commit_group;")
#define CP_WAIT(n)  asm volatile("cp.async.wait_group %0;" :: "n"(n))

// fp32 -> fp16 conversion (vectorized)
__global__ void cvt_f16_kernel(const float4* __restrict__ in, uint2* __restrict__ out, int n4)
{
    int i = blockIdx.x * blockDim.x + threadIdx.x;
    if (i < n4) {
        float4 v = in[i];
        __half2 lo = __floats2half2_rn(v.x, v.y);
        __half2 hi = __floats2half2_rn(v.z, v.w);
        out[i] = make_uint2(*(uint32_t*)&lo, *(uint32_t*)&hi);
    }
}

// ---------------- FP16 tensor-core GEMM ----------------
//   C[M,N] = A[M,K](f16) * B(f16) (+bias) (*scale), accum fp32
//   BT=true : B row-major [N,K] (C = A*B^T); smem tile n-major [128][72]
//   BT=false: B row-major [K,N]; smem tile k-major [64][136], read via ldmatrix.trans
// CTA tile 128x128, BK=64, 128 thr = 4 warps of 64x64 (2x2), 2 CTAs/SM, 3-stage.
// Fat-warp design: fragment crossbar traffic 96KB/tile < tensor 1024 cyc/tile.
// All dims exact tile multiples -> no bounds checks.
template<bool BT, bool BIAS, bool SCALE, bool HALFOUT>
__global__ __launch_bounds__(128, 2)
void gemm_f16_kernel(const __half* __restrict__ A, int lda, long long sA,
                     const __half* __restrict__ B, int ldb, long long sB,
                     float* __restrict__ Cf, int ldc, long long sC,
                     int K, const float* __restrict__ bias, float scale)
{
    constexpr int ALD   = 72;                 // 144B row stride = 9x16B (odd) -> conflict-free
    constexpr int BROWS = BT ? 128 : 64;
    constexpr int BLD   = BT ? 72 : 136;      // 272B = 17x16B (odd)
    constexpr int ASTG  = 128 * ALD;
    constexpr int BSTG  = BROWS * BLD;

    extern __shared__ __half sm[];
    __half* As = sm;                          // [3][128][72]
    __half* Bs = sm + 3 * ASTG;               // [3][BROWS][BLD]

    const int t  = threadIdx.x;
    const int bm = blockIdx.y * 128;
    const int bn = blockIdx.x * 128;
    const __half* Ap = A + (long long)blockIdx.z * sA + (long long)bm * lda;
    const __half* Bp = B + (long long)blockIdx.z * sB
                         + (BT ? (long long)bn * ldb : (long long)bn);
    float*  Cp = Cf + (long long)blockIdx.z * sC;
    __half* Ch = reinterpret_cast<__half*>(Cf) + (long long)blockIdx.z * sC;

    const int warp = t >> 5, lane = t & 31;
    const int wm = (warp & 1) * 64;           // 2 warp rows
    const int wn = (warp >> 1) * 64;          // 2 warp cols
    const int lr = lane >> 2, lc = lane & 3;

    float acc[4][8][4];
#pragma unroll
    for (int i = 0; i < 4; i++)
#pragma unroll
        for (int j = 0; j < 8; j++)
#pragma unroll
            for (int r = 0; r < 4; r++) acc[i][j][r] = 0.f;

    auto load_tiles = [&](int k0, int buf) {
        __half* ad = As + buf * ASTG;
        // A: 128 rows x 64 cols = 1024 x 16B chunks, 128 threads -> 8 each
#pragma unroll
        for (int i = 0; i < 8; i++) {
            const int idx = t + i * 128;          // 0..1023
            const int r = idx >> 3, c8 = (idx & 7) * 8;
            cp16(ad + r * ALD + c8, Ap + (long long)r * lda + k0 + c8);
        }
        __half* bd = Bs + buf * BSTG;
        if (BT) {
#pragma unroll
            for (int i = 0; i < 8; i++) {
                const int idx = t + i * 128;
                const int n = idx >> 3, c8 = (idx & 7) * 8;
                cp16(bd + n * BLD + c8, Bp + (long long)n * ldb + k0 + c8);
            }
        } else {
            // B: 64 rows x 128 cols = 1024 x 16B chunks
#pragma unroll
            for (int i = 0; i < 8; i++) {
                const int idx = t + i * 128;
                const int r = idx >> 4, c8 = (idx & 15) * 8;
                cp16(bd + r * BLD + c8, Bp + (long long)(k0 + r) * ldb + c8);
            }
        }
    };

    // ldmatrix per-lane address components
    const int a_lr = lane & 15;             // matrix row
    const int a_lk = (lane >> 4) << 3;      // k-half select
    const int bt_n = (lane & 7) + ((lane >> 4) & 1) * 8;   // BT: n within 16-group
    const int bt_k = ((lane >> 3) & 1) * 8;                // BT: k-half
    const int bn_k = (lane & 7) + ((lane >> 3) & 1) * 8;   // !BT: k row
    const int bn_n = ((lane >> 4) & 1) * 8;                // !BT: n-half

    const int ntiles = K / 64;              // >= 2 always here
    load_tiles(0, 0);  CP_COMMIT();
    load_tiles(64, 1); CP_COMMIT();

    for (int it = 0; it < ntiles; ++it) {
        if (it + 2 < ntiles) {
            load_tiles((it + 2) * 64, (it + 2) % 3);
            CP_COMMIT();
            CP_WAIT(2);
        } else if (it + 1 < ntiles) {
            CP_WAIT(1);
        } else {
            CP_WAIT(0);
        }
        __syncthreads();

        const int buf = it % 3;
        const __half* Ab = As + buf * ASTG;
        const __half* Bb = Bs + buf * BSTG;
#pragma unroll
        for (int ks = 0; ks < 4; ks++) {
            const int kk = ks * 16;
            uint32_t af[4][4];
#pragma unroll
            for (int mt = 0; mt < 4; mt++) {
                const __half* p = Ab + (wm + mt * 16 + a_lr) * ALD + kk + a_lk;
                ldsm4(af[mt][0], af[mt][1], af[mt][2], af[mt][3],
                      (uint32_t)__cvta_generic_to_shared(p));
            }
            uint32_t bf[8][2];
#pragma unroll
            for (int np = 0; np < 4; np++) {   // nt pair: nt = 2np, 2np+1
                if (BT) {
                    const __half* p = Bb + (wn + np * 16 + bt_n) * BLD + kk + bt_k;
                    ldsm4(bf[np * 2][0], bf[np * 2][1], bf[np * 2 + 1][0], bf[np * 2 + 1][1],
                          (uint32_t)__cvta_generic_to_shared(p));
                } else {
                    const __half* p = Bb + (kk + bn_k) * BLD + wn + np * 16 + bn_n;
                    ldsm4t(bf[np * 2][0], bf[np * 2][1], bf[np * 2 + 1][0], bf[np * 2 + 1][1],
                           (uint32_t)__cvta_generic_to_shared(p));
                }
            }
#pragma unroll
            for (int mt = 0; mt < 4; mt++)
#pragma unroll
                for (int nt = 0; nt < 8; nt++)
                    mma_f16(acc[mt][nt], af[mt], bf[nt]);
        }
        __syncthreads();
    }

    // ---- epilogue ----
#pragma unroll
    for (int mt = 0; mt < 4; mt++) {
#pragma unroll
        for (int nt = 0; nt < 8; nt++) {
            const int r   = bm + wm + mt * 16 + lr;
            const int col = bn + wn + nt * 8 + lc * 2;
            float v0 = acc[mt][nt][0], v1 = acc[mt][nt][1];
            float v2 = acc[mt][nt][2], v3 = acc[mt][nt][3];
            if (BIAS) {
                const float bi0 = bias[col], bi1 = bias[col + 1];
                v0 += bi0; v1 += bi1; v2 += bi0; v3 += bi1;
            }
            if (SCALE) { v0 *= scale; v1 *= scale; v2 *= scale; v3 *= scale; }
            if (HALFOUT) {
                __half2 h01 = __floats2half2_rn(v0, v1);
                __half2 h23 = __floats2half2_rn(v2, v3);
                *reinterpret_cast<__half2*>(&Ch[(long long)r * ldc + col])       = h01;
                *reinterpret_cast<__half2*>(&Ch[(long long)(r + 8) * ldc + col]) = h23;
            } else {
                *reinterpret_cast<float2*>(&Cp[(long long)r * ldc + col])       = make_float2(v0, v1);
                *reinterpret_cast<float2*>(&Cp[(long long)(r + 8) * ldc + col]) = make_float2(v2, v3);
            }
        }
    }
}

// Row softmax: read fp32 S, write fp16 P.
__global__ __launch_bounds__(256)
void softmax_kernel(const float* __restrict__ S, __half* __restrict__ P)
{
    const long long row = blockIdx.x;
    const float* p = S + row * (long long)NN;
    __half* po = P + row * (long long)NN;
    const int t = threadIdx.x;

    float v[8];
    float mx = -1e30f;
#pragma unroll
    for (int i = 0; i < 8; i++) {
        v[i] = p[t + i * 256];
        mx = fmaxf(mx, v[i]);
    }
#pragma unroll
    for (int o = 16; o > 0; o >>= 1)
        mx = fmaxf(mx, __shfl_xor_sync(0xFFFFFFFFu, mx, o));

    __shared__ float redm[8];
    __shared__ float reds[8];
    if ((t & 31) == 0) redm[t >> 5] = mx;
    __syncthreads();
#pragma unroll
    for (int i = 0; i < 8; i++) mx = fmaxf(mx, redm[i]);

    float s = 0.f;
#pragma unroll
    for (int i = 0; i < 8; i++) {
        v[i] = __expf(v[i] - mx);
        s += v[i];
    }
#pragma unroll
    for (int o = 16; o > 0; o >>= 1)
        s += __shfl_xor_sync(0xFFFFFFFFu, s, o);
    if ((t & 31) == 0) reds[t >> 5] = s;
    __syncthreads();
    s = 0.f;
#pragma unroll
    for (int i = 0; i < 8; i++) s += reds[i];

    const float inv = 1.f / s;
#pragma unroll
    for (int i = 0; i < 8; i++)
        po[t + i * 256] = __float2half(v[i] * inv);
}

// ---------------- host ----------------
extern "C" void kernel_launch(void* const* d_in, const int* in_sizes, int n_in,
                              void* d_out, int out_size)
{
    const float* x    = (const float*)d_in[0];   // [8, 2048, 768]
    const float* W    = (const float*)d_in[1];   // [768, 2304]
    const float* bias = (const float*)d_in[2];   // [2304]
    float* out        = (float*)d_out;           // [8, 2048, 768]

    __half *qkv, *ph, *xh, *wh; float *sc;
    cudaGetSymbolAddress((void**)&qkv, g_qkv);
    cudaGetSymbolAddress((void**)&sc,  g_scores);
    cudaGetSymbolAddress((void**)&ph,  g_p);
    cudaGetSymbolAddress((void**)&xh,  g_xh);
    cudaGetSymbolAddress((void**)&wh,  g_wh);

    // Dynamic smem (bytes): BT: 3*(128*72 + 128*72)*2 = 110592 ; !BT: 3*(128*72 + 64*136)*2 = 107520
    const int SM_BT = 3 * (128 * 72 + 128 * 72) * 2;
    const int SM_BN = 3 * (128 * 72 + 64 * 136) * 2;
    cudaFuncSetAttribute(gemm_f16_kernel<false, true,  false, true >,
                         cudaFuncAttributeMaxDynamicSharedMemorySize, SM_BN);
    cudaFuncSetAttribute(gemm_f16_kernel<true,  false, true,  false>,
                         cudaFuncAttributeMaxDynamicSharedMemorySize, SM_BT);
    cudaFuncSetAttribute(gemm_f16_kernel<false, false, false, false>,
                         cudaFuncAttributeMaxDynamicSharedMemorySize, SM_BN);

    const float scale = 0.03608439182435161f;    // 1/sqrt(768)

    // 0) x, W -> fp16
    {
        int n4x = (BB * NN * DD) / 4;
        int n4w = (DD * TRIPLE) / 4;
        cvt_f16_kernel<<<(n4x + 255) / 256, 256>>>((const float4*)x, (uint2*)xh, n4x);
        cvt_f16_kernel<<<(n4w + 255) / 256, 256>>>((const float4*)W, (uint2*)wh, n4w);
    }

    // 1) qkv = xh @ wh + b : M=16384, N=2304, K=768 -> fp16 out
    gemm_f16_kernel<false, true, false, true>
        <<<dim3(TRIPLE / 128, (BB * NN) / 128, 1), 128, SM_BN>>>(
        xh, DD, 0,
        wh, TRIPLE, 0,
        (float*)qkv, TRIPLE, 0,
        DD, bias, 1.f);

    // 2) S = Q @ K^T * scale : per batch M=2048, N=2048, K=768 -> fp32 scores
    gemm_f16_kernel<true, false, true, false>
        <<<dim3(NN / 128, NN / 128, BB), 128, SM_BT>>>(
        qkv,      TRIPLE, (long long)NN * TRIPLE,
        qkv + DD, TRIPLE, (long long)NN * TRIPLE,
        sc,       NN,     (long long)NN * NN,
        DD, nullptr, scale);

    // 3) softmax rows -> fp16 P
    softmax_kernel<<<BB * NN, 256>>>(sc, ph);

    // 4) out = P @ V : per batch M=2048, N=768, K=2048 -> fp32 out
    gemm_f16_kernel<false, false, false, false>
        <<<dim3(DD / 128, NN / 128, BB), 128, SM_BN>>>(
        ph,           NN,     (long long)NN * NN,
        qkv + 2 * DD, TRIPLE, (long long)NN * TRIPLE,
        out,          DD,     (long long)NN * DD,
        NN, nullptr, 1.f);
}

// round 11
// speedup vs baseline: 2.2903x; 1.0451x over previous
#include <cuda_runtime.h>
#include <cuda_fp16.h>
#include <cstdint>

// Problem constants
#define BB 8
#define NN 2048
#define DD 768
#define TRIPLE 2304   // 3*768

// Scratch (device globals; no allocations anywhere)
__device__ __half g_qkv[(size_t)BB * NN * TRIPLE];  // 75 MB fp16 (q,k,v interleaved)
__device__ float  g_scores[(size_t)BB * NN * NN];   // 134 MB fp32
__device__ __half g_p[(size_t)BB * NN * NN];        // 67 MB fp16 softmax probs
__device__ __half g_xh[(size_t)BB * NN * DD];       // 25 MB x in fp16
__device__ __half g_wh[(size_t)DD * TRIPLE];        // 3.5 MB W in fp16

// ---------------- helpers ----------------
__device__ __forceinline__ void mma_f16(float c[4], const uint32_t a[4], const uint32_t b[2]) {
    asm volatile(
        "mma.sync.aligned.m16n8k16.row.col.f32.f16.f16.f32 "
        "{%0,%1,%2,%3}, {%4,%5,%6,%7}, {%8,%9}, {%0,%1,%2,%3};"
        : "+f"(c[0]), "+f"(c[1]), "+f"(c[2]), "+f"(c[3])
        : "r"(a[0]), "r"(a[1]), "r"(a[2]), "r"(a[3]), "r"(b[0]), "r"(b[1]));
}

__device__ __forceinline__ void ldsm4(uint32_t& r0, uint32_t& r1, uint32_t& r2, uint32_t& r3,
                                      uint32_t addr) {
    asm volatile("ldmatrix.sync.aligned.m8n8.x4.shared.b16 {%0,%1,%2,%3}, [%4];"
                 : "=r"(r0), "=r"(r1), "=r"(r2), "=r"(r3) : "r"(addr));
}
__device__ __forceinline__ void ldsm4t(uint32_t& r0, uint32_t& r1, uint32_t& r2, uint32_t& r3,
                                       uint32_t addr) {
    asm volatile("ldmatrix.sync.aligned.m8n8.x4.trans.shared.b16 {%0,%1,%2,%3}, [%4];"
                 : "=r"(r0), "=r"(r1), "=r"(r2), "=r"(r3) : "r"(addr));
}

__device__ __forceinline__ void cp16(const __half* dst_smem, const __half* src) {
    uint32_t d = (uint32_t)__cvta_generic_to_shared(dst_smem);
    asm volatile("cp.async.cg.shared.global [%0], [%1], 16;" :: "r"(d), "l"(src));
}
#define CP_COMMIT() asm volatile("cp.async.commit_group;")
#define CP_WAIT(n)  asm volatile("cp.async.wait_group %0;" :: "n"(n))

// fp32 -> fp16 conversion (vectorized)
__global__ void cvt_f16_kernel(const float4* __restrict__ in, uint2* __restrict__ out, int n4)
{
    int i = blockIdx.x * blockDim.x + threadIdx.x;
    if (i < n4) {
        float4 v = in[i];
        __half2 lo = __floats2half2_rn(v.x, v.y);
        __half2 hi = __floats2half2_rn(v.z, v.w);
        out[i] = make_uint2(*(uint32_t*)&lo, *(uint32_t*)&hi);
    }
}

// ---------------- FP16 tensor-core GEMM ----------------
//   C[M,N] = A[M,K](f16) * B(f16) (+bias) (*scale), accum fp32
//   BT=true : B row-major [N,K] (C = A*B^T); smem tile n-major [128][72]
//   BT=false: B row-major [K,N]; smem tile k-major [64][136], read via ldmatrix.trans
// CTA tile 128x128, BK=64, 128 thr = 4 warps of 64x64 (2x2), 2 CTAs/SM, 3-stage.
// Single-barrier mainloop: wait -> barrier -> compute(it) -> load(it+2).
//   visibility: per-thread CP_WAIT then barrier => tile it visible to all.
//   WAR: load(it+2) targets buf (it-1)%3 != it%3; a warp reaching load(it+3)
//        (-> buf it%3) passed barrier(it+1), i.e. all warps finished compute(it).
template<bool BT, bool BIAS, bool SCALE, bool HALFOUT>
__global__ __launch_bounds__(128, 2)
void gemm_f16_kernel(const __half* __restrict__ A, int lda, long long sA,
                     const __half* __restrict__ B, int ldb, long long sB,
                     float* __restrict__ Cf, int ldc, long long sC,
                     int K, const float* __restrict__ bias, float scale)
{
    constexpr int ALD   = 72;                 // 144B row stride = 9x16B (odd) -> conflict-free
    constexpr int BROWS = BT ? 128 : 64;
    constexpr int BLD   = BT ? 72 : 136;      // 272B = 17x16B (odd)
    constexpr int ASTG  = 128 * ALD;
    constexpr int BSTG  = BROWS * BLD;

    extern __shared__ __half sm[];
    __half* As = sm;                          // [3][128][72]
    __half* Bs = sm + 3 * ASTG;               // [3][BROWS][BLD]

    const int t  = threadIdx.x;
    const int bm = blockIdx.y * 128;
    const int bn = blockIdx.x * 128;
    const __half* Ap = A + (long long)blockIdx.z * sA + (long long)bm * lda;
    const __half* Bp = B + (long long)blockIdx.z * sB
                         + (BT ? (long long)bn * ldb : (long long)bn);
    float*  Cp = Cf + (long long)blockIdx.z * sC;
    __half* Ch = reinterpret_cast<__half*>(Cf) + (long long)blockIdx.z * sC;

    const int warp = t >> 5, lane = t & 31;
    const int wm = (warp & 1) * 64;           // 2 warp rows
    const int wn = (warp >> 1) * 64;          // 2 warp cols
    const int lr = lane >> 2, lc = lane & 3;

    float acc[4][8][4];
#pragma unroll
    for (int i = 0; i < 4; i++)
#pragma unroll
        for (int j = 0; j < 8; j++)
#pragma unroll
            for (int r = 0; r < 4; r++) acc[i][j][r] = 0.f;

    auto load_tiles = [&](int k0, int buf) {
        __half* ad = As + buf * ASTG;
        // A: 128 rows x 64 cols = 1024 x 16B chunks, 128 threads -> 8 each
#pragma unroll
        for (int i = 0; i < 8; i++) {
            const int idx = t + i * 128;          // 0..1023
            const int r = idx >> 3, c8 = (idx & 7) * 8;
            cp16(ad + r * ALD + c8, Ap + (long long)r * lda + k0 + c8);
        }
        __half* bd = Bs + buf * BSTG;
        if (BT) {
#pragma unroll
            for (int i = 0; i < 8; i++) {
                const int idx = t + i * 128;
                const int n = idx >> 3, c8 = (idx & 7) * 8;
                cp16(bd + n * BLD + c8, Bp + (long long)n * ldb + k0 + c8);
            }
        } else {
            // B: 64 rows x 128 cols = 1024 x 16B chunks
#pragma unroll
            for (int i = 0; i < 8; i++) {
                const int idx = t + i * 128;
                const int r = idx >> 4, c8 = (idx & 15) * 8;
                cp16(bd + r * BLD + c8, Bp + (long long)(k0 + r) * ldb + c8);
            }
        }
    };

    // ldmatrix per-lane address components
    const int a_lr = lane & 15;             // matrix row
    const int a_lk = (lane >> 4) << 3;      // k-half select
    const int bt_n = (lane & 7) + ((lane >> 4) & 1) * 8;   // BT: n within 16-group
    const int bt_k = ((lane >> 3) & 1) * 8;                // BT: k-half
    const int bn_k = (lane & 7) + ((lane >> 3) & 1) * 8;   // !BT: k row
    const int bn_n = ((lane >> 4) & 1) * 8;                // !BT: n-half

    const int ntiles = K / 64;              // >= 2 always here
    load_tiles(0, 0);  CP_COMMIT();
    load_tiles(64, 1); CP_COMMIT();

    for (int it = 0; it < ntiles; ++it) {
        if (it + 1 < ntiles) { CP_WAIT(1); } else { CP_WAIT(0); }
        __syncthreads();

        const int buf = it % 3;
        const __half* Ab = As + buf * ASTG;
        const __half* Bb = Bs + buf * BSTG;
#pragma unroll
        for (int ks = 0; ks < 4; ks++) {
            const int kk = ks * 16;
            uint32_t af[4][4];
#pragma unroll
            for (int mt = 0; mt < 4; mt++) {
                const __half* p = Ab + (wm + mt * 16 + a_lr) * ALD + kk + a_lk;
                ldsm4(af[mt][0], af[mt][1], af[mt][2], af[mt][3],
                      (uint32_t)__cvta_generic_to_shared(p));
            }
            uint32_t bf[8][2];
#pragma unroll
            for (int np = 0; np < 4; np++) {   // nt pair: nt = 2np, 2np+1
                if (BT) {
                    const __half* p = Bb + (wn + np * 16 + bt_n) * BLD + kk + bt_k;
                    ldsm4(bf[np * 2][0], bf[np * 2][1], bf[np * 2 + 1][0], bf[np * 2 + 1][1],
                          (uint32_t)__cvta_generic_to_shared(p));
                } else {
                    const __half* p = Bb + (kk + bn_k) * BLD + wn + np * 16 + bn_n;
                    ldsm4t(bf[np * 2][0], bf[np * 2][1], bf[np * 2 + 1][0], bf[np * 2 + 1][1],
                           (uint32_t)__cvta_generic_to_shared(p));
                }
            }
#pragma unroll
            for (int mt = 0; mt < 4; mt++)
#pragma unroll
                for (int nt = 0; nt < 8; nt++)
                    mma_f16(acc[mt][nt], af[mt], bf[nt]);
        }

        if (it + 2 < ntiles) {
            load_tiles((it + 2) * 64, (it + 2) % 3);
            CP_COMMIT();
        }
    }

    // ---- epilogue ----
#pragma unroll
    for (int mt = 0; mt < 4; mt++) {
#pragma unroll
        for (int nt = 0; nt < 8; nt++) {
            const int r   = bm + wm + mt * 16 + lr;
            const int col = bn + wn + nt * 8 + lc * 2;
            float v0 = acc[mt][nt][0], v1 = acc[mt][nt][1];
            float v2 = acc[mt][nt][2], v3 = acc[mt][nt][3];
            if (BIAS) {
                const float bi0 = bias[col], bi1 = bias[col + 1];
                v0 += bi0; v1 += bi1; v2 += bi0; v3 += bi1;
            }
            if (SCALE) { v0 *= scale; v1 *= scale; v2 *= scale; v3 *= scale; }
            if (HALFOUT) {
                __half2 h01 = __floats2half2_rn(v0, v1);
                __half2 h23 = __floats2half2_rn(v2, v3);
                *reinterpret_cast<__half2*>(&Ch[(long long)r * ldc + col])       = h01;
                *reinterpret_cast<__half2*>(&Ch[(long long)(r + 8) * ldc + col]) = h23;
            } else {
                *reinterpret_cast<float2*>(&Cp[(long long)r * ldc + col])       = make_float2(v0, v1);
                *reinterpret_cast<float2*>(&Cp[(long long)(r + 8) * ldc + col]) = make_float2(v2, v3);
            }
        }
    }
}

// Row softmax: read fp32 S, write fp16 P.
__global__ __launch_bounds__(256)
void softmax_kernel(const float* __restrict__ S, __half* __restrict__ P)
{
    const long long row = blockIdx.x;
    const float* p = S + row * (long long)NN;
    __half* po = P + row * (long long)NN;
    const int t = threadIdx.x;

    float v[8];
    float mx = -1e30f;
#pragma unroll
    for (int i = 0; i < 8; i++) {
        v[i] = p[t + i * 256];
        mx = fmaxf(mx, v[i]);
    }
#pragma unroll
    for (int o = 16; o > 0; o >>= 1)
        mx = fmaxf(mx, __shfl_xor_sync(0xFFFFFFFFu, mx, o));

    __shared__ float redm[8];
    __shared__ float reds[8];
    if ((t & 31) == 0) redm[t >> 5] = mx;
    __syncthreads();
#pragma unroll
    for (int i = 0; i < 8; i++) mx = fmaxf(mx, redm[i]);

    float s = 0.f;
#pragma unroll
    for (int i = 0; i < 8; i++) {
        v[i] = __expf(v[i] - mx);
        s += v[i];
    }
#pragma unroll
    for (int o = 16; o > 0; o >>= 1)
        s += __shfl_xor_sync(0xFFFFFFFFu, s, o);
    if ((t & 31) == 0) reds[t >> 5] = s;
    __syncthreads();
    s = 0.f;
#pragma unroll
    for (int i = 0; i < 8; i++) s += reds[i];

    const float inv = 1.f / s;
#pragma unroll
    for (int i = 0; i < 8; i++)
        po[t + i * 256] = __float2half(v[i] * inv);
}

// ---------------- host ----------------
extern "C" void kernel_launch(void* const* d_in, const int* in_sizes, int n_in,
                              void* d_out, int out_size)
{
    const float* x    = (const float*)d_in[0];   // [8, 2048, 768]
    const float* W    = (const float*)d_in[1];   // [768, 2304]
    const float* bias = (const float*)d_in[2];   // [2304]
    float* out        = (float*)d_out;           // [8, 2048, 768]

    __half *qkv, *ph, *xh, *wh; float *sc;
    cudaGetSymbolAddress((void**)&qkv, g_qkv);
    cudaGetSymbolAddress((void**)&sc,  g_scores);
    cudaGetSymbolAddress((void**)&ph,  g_p);
    cudaGetSymbolAddress((void**)&xh,  g_xh);
    cudaGetSymbolAddress((void**)&wh,  g_wh);

    // Dynamic smem (bytes): BT: 3*(128*72 + 128*72)*2 = 110592 ; !BT: 3*(128*72 + 64*136)*2 = 107520
    const int SM_BT = 3 * (128 * 72 + 128 * 72) * 2;
    const int SM_BN = 3 * (128 * 72 + 64 * 136) * 2;
    cudaFuncSetAttribute(gemm_f16_kernel<false, true,  false, true >,
                         cudaFuncAttributeMaxDynamicSharedMemorySize, SM_BN);
    cudaFuncSetAttribute(gemm_f16_kernel<true,  false, true,  false>,
                         cudaFuncAttributeMaxDynamicSharedMemorySize, SM_BT);
    cudaFuncSetAttribute(gemm_f16_kernel<false, false, false, false>,
                         cudaFuncAttributeMaxDynamicSharedMemorySize, SM_BN);

    const float scale = 0.03608439182435161f;    // 1/sqrt(768)

    // 0) x, W -> fp16
    {
        int n4x = (BB * NN * DD) / 4;
        int n4w = (DD * TRIPLE) / 4;
        cvt_f16_kernel<<<(n4x + 255) / 256, 256>>>((const float4*)x, (uint2*)xh, n4x);
        cvt_f16_kernel<<<(n4w + 255) / 256, 256>>>((const float4*)W, (uint2*)wh, n4w);
    }

    // 1) qkv = xh @ wh + b : M=16384, N=2304, K=768 -> fp16 out
    gemm_f16_kernel<false, true, false, true>
        <<<dim3(TRIPLE / 128, (BB * NN) / 128, 1), 128, SM_BN>>>(
        xh, DD, 0,
        wh, TRIPLE, 0,
        (float*)qkv, TRIPLE, 0,
        DD, bias, 1.f);

    // 2) S = Q @ K^T * scale : per batch M=2048, N=2048, K=768 -> fp32 scores
    gemm_f16_kernel<true, false, true, false>
        <<<dim3(NN / 128, NN / 128, BB), 128, SM_BT>>>(
        qkv,      TRIPLE, (long long)NN * TRIPLE,
        qkv + DD, TRIPLE, (long long)NN * TRIPLE,
        sc,       NN,     (long long)NN * NN,
        DD, nullptr, scale);

    // 3) softmax rows -> fp16 P
    softmax_kernel<<<BB * NN, 256>>>(sc, ph);

    // 4) out = P @ V : per batch M=2048, N=768, K=2048 -> fp32 out
    gemm_f16_kernel<false, false, false, false>
        <<<dim3(DD / 128, NN / 128, BB), 128, SM_BN>>>(
        ph,           NN,     (long long)NN * NN,
        qkv + 2 * DD, TRIPLE, (long long)NN * TRIPLE,
        out,          DD,     (long long)NN * DD,
        NN, nullptr, 1.f);
}

// round 12
// speedup vs baseline: 2.3060x; 1.0069x over previous
#include <cuda_runtime.h>
#include <cuda_fp16.h>
#include <cstdint>

// Problem constants
#define BB 8
#define NN 2048
#define DD 768
#define TRIPLE 2304   // 3*768

// Scratch (device globals; no allocations anywhere)
__device__ __half g_qkv[(size_t)BB * NN * TRIPLE];  // 75 MB fp16 (q,k,v interleaved)
__device__ float  g_scores[(size_t)BB * NN * NN];   // 134 MB fp32
__device__ __half g_p[(size_t)BB * NN * NN];        // 67 MB fp16 softmax probs
__device__ __half g_xh[(size_t)BB * NN * DD];       // 25 MB x in fp16
__device__ __half g_wh[(size_t)DD * TRIPLE];        // 3.5 MB W in fp16

// ---------------- helpers ----------------
__device__ __forceinline__ void mma_f16(float c[4], const uint32_t a[4], const uint32_t b[2]) {
    asm volatile(
        "mma.sync.aligned.m16n8k16.row.col.f32.f16.f16.f32 "
        "{%0,%1,%2,%3}, {%4,%5,%6,%7}, {%8,%9}, {%0,%1,%2,%3};"
        : "+f"(c[0]), "+f"(c[1]), "+f"(c[2]), "+f"(c[3])
        : "r"(a[0]), "r"(a[1]), "r"(a[2]), "r"(a[3]), "r"(b[0]), "r"(b[1]));
}

__device__ __forceinline__ void ldsm4(uint32_t& r0, uint32_t& r1, uint32_t& r2, uint32_t& r3,
                                      uint32_t addr) {
    asm volatile("ldmatrix.sync.aligned.m8n8.x4.shared.b16 {%0,%1,%2,%3}, [%4];"
                 : "=r"(r0), "=r"(r1), "=r"(r2), "=r"(r3) : "r"(addr));
}
__device__ __forceinline__ void ldsm4t(uint32_t& r0, uint32_t& r1, uint32_t& r2, uint32_t& r3,
                                       uint32_t addr) {
    asm volatile("ldmatrix.sync.aligned.m8n8.x4.trans.shared.b16 {%0,%1,%2,%3}, [%4];"
                 : "=r"(r0), "=r"(r1), "=r"(r2), "=r"(r3) : "r"(addr));
}

__device__ __forceinline__ void cp16(const __half* dst_smem, const __half* src) {
    uint32_t d = (uint32_t)__cvta_generic_to_shared(dst_smem);
    asm volatile("cp.async.cg.shared.global [%0], [%1], 16;" :: "r"(d), "l"(src));
}
#define CP_COMMIT() asm volatile("cp.async.commit_group;")
#define CP_WAIT(n)  asm volatile("cp.async.wait_group %0;" :: "n"(n))

// fp32 -> fp16 conversion (vectorized)
__global__ void cvt_f16_kernel(const float4* __restrict__ in, uint2* __restrict__ out, int n4)
{
    int i = blockIdx.x * blockDim.x + threadIdx.x;
    if (i < n4) {
        float4 v = in[i];
        __half2 lo = __floats2half2_rn(v.x, v.y);
        __half2 hi = __floats2half2_rn(v.z, v.w);
        out[i] = make_uint2(*(uint32_t*)&lo, *(uint32_t*)&hi);
    }
}

// ---------------- FP16 tensor-core GEMM ----------------
//   C[M,N] = A[M,K](f16) * B(f16) (+bias) (*scale), accum fp32
//   BT=true : B row-major [N,K] (C = A*B^T); smem tile n-major [128][72]
//   BT=false: B row-major [K,N]; smem tile k-major [64][136], read via ldmatrix.trans
// CTA tile 128x128, BK=64, 128 thr = 4 warps of 64x64 (2x2), 2 CTAs/SM, 3-stage.
// Single-barrier mainloop + register-level fragment pipelining:
//   bf double-buffered across ksteps (next-kstep B LDSMs shadow current MMAs);
//   af loaded per-mt (short liveness -> ptxas overlaps mt+1 fetch with mt MMAs).
template<bool BT, bool BIAS, bool SCALE, bool HALFOUT>
__global__ __launch_bounds__(128, 2)
void gemm_f16_kernel(const __half* __restrict__ A, int lda, long long sA,
                     const __half* __restrict__ B, int ldb, long long sB,
                     float* __restrict__ Cf, int ldc, long long sC,
                     int K, const float* __restrict__ bias, float scale)
{
    constexpr int ALD   = 72;                 // 144B row stride = 9x16B (odd) -> conflict-free
    constexpr int BROWS = BT ? 128 : 64;
    constexpr int BLD   = BT ? 72 : 136;      // 272B = 17x16B (odd)
    constexpr int ASTG  = 128 * ALD;
    constexpr int BSTG  = BROWS * BLD;

    extern __shared__ __half sm[];
    __half* As = sm;                          // [3][128][72]
    __half* Bs = sm + 3 * ASTG;               // [3][BROWS][BLD]

    const int t  = threadIdx.x;
    const int bm = blockIdx.y * 128;
    const int bn = blockIdx.x * 128;
    const __half* Ap = A + (long long)blockIdx.z * sA + (long long)bm * lda;
    const __half* Bp = B + (long long)blockIdx.z * sB
                         + (BT ? (long long)bn * ldb : (long long)bn);
    float*  Cp = Cf + (long long)blockIdx.z * sC;
    __half* Ch = reinterpret_cast<__half*>(Cf) + (long long)blockIdx.z * sC;

    const int warp = t >> 5, lane = t & 31;
    const int wm = (warp & 1) * 64;           // 2 warp rows
    const int wn = (warp >> 1) * 64;          // 2 warp cols
    const int lr = lane >> 2, lc = lane & 3;

    float acc[4][8][4];
#pragma unroll
    for (int i = 0; i < 4; i++)
#pragma unroll
        for (int j = 0; j < 8; j++)
#pragma unroll
            for (int r = 0; r < 4; r++) acc[i][j][r] = 0.f;

    auto load_tiles = [&](int k0, int buf) {
        __half* ad = As + buf * ASTG;
        // A: 128 rows x 64 cols = 1024 x 16B chunks, 128 threads -> 8 each
#pragma unroll
        for (int i = 0; i < 8; i++) {
            const int idx = t + i * 128;          // 0..1023
            const int r = idx >> 3, c8 = (idx & 7) * 8;
            cp16(ad + r * ALD + c8, Ap + (long long)r * lda + k0 + c8);
        }
        __half* bd = Bs + buf * BSTG;
        if (BT) {
#pragma unroll
            for (int i = 0; i < 8; i++) {
                const int idx = t + i * 128;
                const int n = idx >> 3, c8 = (idx & 7) * 8;
                cp16(bd + n * BLD + c8, Bp + (long long)n * ldb + k0 + c8);
            }
        } else {
            // B: 64 rows x 128 cols = 1024 x 16B chunks
#pragma unroll
            for (int i = 0; i < 8; i++) {
                const int idx = t + i * 128;
                const int r = idx >> 4, c8 = (idx & 15) * 8;
                cp16(bd + r * BLD + c8, Bp + (long long)(k0 + r) * ldb + c8);
            }
        }
    };

    // ldmatrix per-lane address components
    const int a_lr = lane & 15;             // matrix row
    const int a_lk = (lane >> 4) << 3;      // k-half select
    const int bt_n = (lane & 7) + ((lane >> 4) & 1) * 8;   // BT: n within 16-group
    const int bt_k = ((lane >> 3) & 1) * 8;                // BT: k-half
    const int bn_k = (lane & 7) + ((lane >> 3) & 1) * 8;   // !BT: k row
    const int bn_n = ((lane >> 4) & 1) * 8;                // !BT: n-half

    // load all 8 B fragments for k-offset kk into bf
    auto load_bf = [&](uint32_t (&bf)[8][2], const __half* Bb, int kk) {
#pragma unroll
        for (int np = 0; np < 4; np++) {
            if (BT) {
                const __half* p = Bb + (wn + np * 16 + bt_n) * BLD + kk + bt_k;
                ldsm4(bf[np * 2][0], bf[np * 2][1], bf[np * 2 + 1][0], bf[np * 2 + 1][1],
                      (uint32_t)__cvta_generic_to_shared(p));
            } else {
                const __half* p = Bb + (kk + bn_k) * BLD + wn + np * 16 + bn_n;
                ldsm4t(bf[np * 2][0], bf[np * 2][1], bf[np * 2 + 1][0], bf[np * 2 + 1][1],
                       (uint32_t)__cvta_generic_to_shared(p));
            }
        }
    };

    const int ntiles = K / 64;              // >= 2 always here
    load_tiles(0, 0);  CP_COMMIT();
    load_tiles(64, 1); CP_COMMIT();

    uint32_t bfb[2][8][2];                  // B fragments, double-buffered across ksteps

    for (int it = 0; it < ntiles; ++it) {
        if (it + 1 < ntiles) { CP_WAIT(1); } else { CP_WAIT(0); }
        __syncthreads();

        const int buf = it % 3;
        const __half* Ab = As + buf * ASTG;
        const __half* Bb = Bs + buf * BSTG;

        load_bf(bfb[0], Bb, 0);             // kstep 0 B fragments
#pragma unroll
        for (int ks = 0; ks < 4; ks++) {
            const int kk = ks * 16;
            if (ks < 3) load_bf(bfb[(ks + 1) & 1], Bb, kk + 16);  // shadow under MMAs
            const uint32_t (&bf)[8][2] = bfb[ks & 1];
#pragma unroll
            for (int mt = 0; mt < 4; mt++) {
                uint32_t af[4];
                const __half* p = Ab + (wm + mt * 16 + a_lr) * ALD + kk + a_lk;
                ldsm4(af[0], af[1], af[2], af[3],
                      (uint32_t)__cvta_generic_to_shared(p));
#pragma unroll
                for (int nt = 0; nt < 8; nt++)
                    mma_f16(acc[mt][nt], af, bf[nt]);
            }
        }

        if (it + 2 < ntiles) {
            load_tiles((it + 2) * 64, (it + 2) % 3);
            CP_COMMIT();
        }
    }

    // ---- epilogue ----
#pragma unroll
    for (int mt = 0; mt < 4; mt++) {
#pragma unroll
        for (int nt = 0; nt < 8; nt++) {
            const int r   = bm + wm + mt * 16 + lr;
            const int col = bn + wn + nt * 8 + lc * 2;
            float v0 = acc[mt][nt][0], v1 = acc[mt][nt][1];
            float v2 = acc[mt][nt][2], v3 = acc[mt][nt][3];
            if (BIAS) {
                const float bi0 = bias[col], bi1 = bias[col + 1];
                v0 += bi0; v1 += bi1; v2 += bi0; v3 += bi1;
            }
            if (SCALE) { v0 *= scale; v1 *= scale; v2 *= scale; v3 *= scale; }
            if (HALFOUT) {
                __half2 h01 = __floats2half2_rn(v0, v1);
                __half2 h23 = __floats2half2_rn(v2, v3);
                *reinterpret_cast<__half2*>(&Ch[(long long)r * ldc + col])       = h01;
                *reinterpret_cast<__half2*>(&Ch[(long long)(r + 8) * ldc + col]) = h23;
            } else {
                *reinterpret_cast<float2*>(&Cp[(long long)r * ldc + col])       = make_float2(v0, v1);
                *reinterpret_cast<float2*>(&Cp[(long long)(r + 8) * ldc + col]) = make_float2(v2, v3);
            }
        }
    }
}

// Row softmax: read fp32 S, write fp16 P.
__global__ __launch_bounds__(256)
void softmax_kernel(const float* __restrict__ S, __half* __restrict__ P)
{
    const long long row = blockIdx.x;
    const float* p = S + row * (long long)NN;
    __half* po = P + row * (long long)NN;
    const int t = threadIdx.x;

    float v[8];
    float mx = -1e30f;
#pragma unroll
    for (int i = 0; i < 8; i++) {
        v[i] = p[t + i * 256];
        mx = fmaxf(mx, v[i]);
    }
#pragma unroll
    for (int o = 16; o > 0; o >>= 1)
        mx = fmaxf(mx, __shfl_xor_sync(0xFFFFFFFFu, mx, o));

    __shared__ float redm[8];
    __shared__ float reds[8];
    if ((t & 31) == 0) redm[t >> 5] = mx;
    __syncthreads();
#pragma unroll
    for (int i = 0; i < 8; i++) mx = fmaxf(mx, redm[i]);

    float s = 0.f;
#pragma unroll
    for (int i = 0; i < 8; i++) {
        v[i] = __expf(v[i] - mx);
        s += v[i];
    }
#pragma unroll
    for (int o = 16; o > 0; o >>= 1)
        s += __shfl_xor_sync(0xFFFFFFFFu, s, o);
    if ((t & 31) == 0) reds[t >> 5] = s;
    __syncthreads();
    s = 0.f;
#pragma unroll
    for (int i = 0; i < 8; i++) s += reds[i];

    const float inv = 1.f / s;
#pragma unroll
    for (int i = 0; i < 8; i++)
        po[t + i * 256] = __float2half(v[i] * inv);
}

// ---------------- host ----------------
extern "C" void kernel_launch(void* const* d_in, const int* in_sizes, int n_in,
                              void* d_out, int out_size)
{
    const float* x    = (const float*)d_in[0];   // [8, 2048, 768]
    const float* W    = (const float*)d_in[1];   // [768, 2304]
    const float* bias = (const float*)d_in[2];   // [2304]
    float* out        = (float*)d_out;           // [8, 2048, 768]

    __half *qkv, *ph, *xh, *wh; float *sc;
    cudaGetSymbolAddress((void**)&qkv, g_qkv);
    cudaGetSymbolAddress((void**)&sc,  g_scores);
    cudaGetSymbolAddress((void**)&ph,  g_p);
    cudaGetSymbolAddress((void**)&xh,  g_xh);
    cudaGetSymbolAddress((void**)&wh,  g_wh);

    // Dynamic smem (bytes): BT: 3*(128*72 + 128*72)*2 = 110592 ; !BT: 3*(128*72 + 64*136)*2 = 107520
    const int SM_BT = 3 * (128 * 72 + 128 * 72) * 2;
    const int SM_BN = 3 * (128 * 72 + 64 * 136) * 2;
    cudaFuncSetAttribute(gemm_f16_kernel<false, true,  false, true >,
                         cudaFuncAttributeMaxDynamicSharedMemorySize, SM_BN);
    cudaFuncSetAttribute(gemm_f16_kernel<true,  false, true,  false>,
                         cudaFuncAttributeMaxDynamicSharedMemorySize, SM_BT);
    cudaFuncSetAttribute(gemm_f16_kernel<false, false, false, false>,
                         cudaFuncAttributeMaxDynamicSharedMemorySize, SM_BN);

    const float scale = 0.03608439182435161f;    // 1/sqrt(768)

    // 0) x, W -> fp16
    {
        int n4x = (BB * NN * DD) / 4;
        int n4w = (DD * TRIPLE) / 4;
        cvt_f16_kernel<<<(n4x + 255) / 256, 256>>>((const float4*)x, (uint2*)xh, n4x);
        cvt_f16_kernel<<<(n4w + 255) / 256, 256>>>((const float4*)W, (uint2*)wh, n4w);
    }

    // 1) qkv = xh @ wh + b : M=16384, N=2304, K=768 -> fp16 out
    gemm_f16_kernel<false, true, false, true>
        <<<dim3(TRIPLE / 128, (BB * NN) / 128, 1), 128, SM_BN>>>(
        xh, DD, 0,
        wh, TRIPLE, 0,
        (float*)qkv, TRIPLE, 0,
        DD, bias, 1.f);

    // 2) S = Q @ K^T * scale : per batch M=2048, N=2048, K=768 -> fp32 scores
    gemm_f16_kernel<true, false, true, false>
        <<<dim3(NN / 128, NN / 128, BB), 128, SM_BT>>>(
        qkv,      TRIPLE, (long long)NN * TRIPLE,
        qkv + DD, TRIPLE, (long long)NN * TRIPLE,
        sc,       NN,     (long long)NN * NN,
        DD, nullptr, scale);

    // 3) softmax rows -> fp16 P
    softmax_kernel<<<BB * NN, 256>>>(sc, ph);

    // 4) out = P @ V : per batch M=2048, N=768, K=2048 -> fp32 out
    gemm_f16_kernel<false, false, false, false>
        <<<dim3(DD / 128, NN / 128, BB), 128, SM_BN>>>(
        ph,           NN,     (long long)NN * NN,
        qkv + 2 * DD, TRIPLE, (long long)NN * TRIPLE,
        out,          DD,     (long long)NN * DD,
        NN, nullptr, 1.f);
}

// round 13
// speedup vs baseline: 2.3449x; 1.0169x over previous
#include <cuda_runtime.h>
#include <cuda_fp16.h>
#include <cstdint>

// Problem constants
#define BB 8
#define NN 2048
#define DD 768
#define TRIPLE 2304   // 3*768

// Scratch (device globals; no allocations anywhere)
__device__ __half g_qkv[(size_t)BB * NN * TRIPLE];  // 75 MB fp16 (q,k,v interleaved)
__device__ __half g_s[(size_t)BB * NN * NN];        // 67 MB fp16 scores
__device__ __half g_p[(size_t)BB * NN * NN];        // 67 MB fp16 softmax probs
__device__ __half g_xh[(size_t)BB * NN * DD];       // 25 MB x in fp16
__device__ __half g_wh[(size_t)DD * TRIPLE];        // 3.5 MB W in fp16

// ---------------- helpers ----------------
__device__ __forceinline__ void mma_f16(float c[4], const uint32_t a[4], const uint32_t b[2]) {
    asm volatile(
        "mma.sync.aligned.m16n8k16.row.col.f32.f16.f16.f32 "
        "{%0,%1,%2,%3}, {%4,%5,%6,%7}, {%8,%9}, {%0,%1,%2,%3};"
        : "+f"(c[0]), "+f"(c[1]), "+f"(c[2]), "+f"(c[3])
        : "r"(a[0]), "r"(a[1]), "r"(a[2]), "r"(a[3]), "r"(b[0]), "r"(b[1]));
}

__device__ __forceinline__ void ldsm4(uint32_t& r0, uint32_t& r1, uint32_t& r2, uint32_t& r3,
                                      uint32_t addr) {
    asm volatile("ldmatrix.sync.aligned.m8n8.x4.shared.b16 {%0,%1,%2,%3}, [%4];"
                 : "=r"(r0), "=r"(r1), "=r"(r2), "=r"(r3) : "r"(addr));
}
__device__ __forceinline__ void ldsm4t(uint32_t& r0, uint32_t& r1, uint32_t& r2, uint32_t& r3,
                                       uint32_t addr) {
    asm volatile("ldmatrix.sync.aligned.m8n8.x4.trans.shared.b16 {%0,%1,%2,%3}, [%4];"
                 : "=r"(r0), "=r"(r1), "=r"(r2), "=r"(r3) : "r"(addr));
}

__device__ __forceinline__ void cp16(const __half* dst_smem, const __half* src) {
    uint32_t d = (uint32_t)__cvta_generic_to_shared(dst_smem);
    asm volatile("cp.async.cg.shared.global [%0], [%1], 16;" :: "r"(d), "l"(src));
}
#define CP_COMMIT() asm volatile("cp.async.commit_group;")
#define CP_WAIT(n)  asm volatile("cp.async.wait_group %0;" :: "n"(n))

// fp32 -> fp16 conversion (vectorized)
__global__ void cvt_f16_kernel(const float4* __restrict__ in, uint2* __restrict__ out, int n4)
{
    int i = blockIdx.x * blockDim.x + threadIdx.x;
    if (i < n4) {
        float4 v = in[i];
        __half2 lo = __floats2half2_rn(v.x, v.y);
        __half2 hi = __floats2half2_rn(v.z, v.w);
        out[i] = make_uint2(*(uint32_t*)&lo, *(uint32_t*)&hi);
    }
}

// ---------------- FP16 tensor-core GEMM ----------------
//   C[M,N] = A[M,K](f16) * B(f16) (+bias) (*scale), accum fp32
//   BT=true : B row-major [N,K] (C = A*B^T); smem tile n-major [128][72]
//   BT=false: B row-major [K,N]; smem tile k-major [64][136], read via ldmatrix.trans
// CTA tile 128x128, BK=64, 128 thr = 4 warps of 64x64 (2x2), 2 CTAs/SM, 3-stage.
// Single-barrier mainloop + register-level fragment pipelining (frozen since R12;
// legacy-HMMA pipe measured at its ~60% structural ceiling across 5 variants).
template<bool BT, bool BIAS, bool SCALE, bool HALFOUT>
__global__ __launch_bounds__(128, 2)
void gemm_f16_kernel(const __half* __restrict__ A, int lda, long long sA,
                     const __half* __restrict__ B, int ldb, long long sB,
                     float* __restrict__ Cf, int ldc, long long sC,
                     int K, const float* __restrict__ bias, float scale)
{
    constexpr int ALD   = 72;                 // 144B row stride = 9x16B (odd) -> conflict-free
    constexpr int BROWS = BT ? 128 : 64;
    constexpr int BLD   = BT ? 72 : 136;      // 272B = 17x16B (odd)
    constexpr int ASTG  = 128 * ALD;
    constexpr int BSTG  = BROWS * BLD;

    extern __shared__ __half sm[];
    __half* As = sm;                          // [3][128][72]
    __half* Bs = sm + 3 * ASTG;               // [3][BROWS][BLD]

    const int t  = threadIdx.x;
    const int bm = blockIdx.y * 128;
    const int bn = blockIdx.x * 128;
    const __half* Ap = A + (long long)blockIdx.z * sA + (long long)bm * lda;
    const __half* Bp = B + (long long)blockIdx.z * sB
                         + (BT ? (long long)bn * ldb : (long long)bn);
    float*  Cp = Cf + (long long)blockIdx.z * sC;
    __half* Ch = reinterpret_cast<__half*>(Cf) + (long long)blockIdx.z * sC;

    const int warp = t >> 5, lane = t & 31;
    const int wm = (warp & 1) * 64;           // 2 warp rows
    const int wn = (warp >> 1) * 64;          // 2 warp cols
    const int lr = lane >> 2, lc = lane & 3;

    float acc[4][8][4];
#pragma unroll
    for (int i = 0; i < 4; i++)
#pragma unroll
        for (int j = 0; j < 8; j++)
#pragma unroll
            for (int r = 0; r < 4; r++) acc[i][j][r] = 0.f;

    auto load_tiles = [&](int k0, int buf) {
        __half* ad = As + buf * ASTG;
        // A: 128 rows x 64 cols = 1024 x 16B chunks, 128 threads -> 8 each
#pragma unroll
        for (int i = 0; i < 8; i++) {
            const int idx = t + i * 128;          // 0..1023
            const int r = idx >> 3, c8 = (idx & 7) * 8;
            cp16(ad + r * ALD + c8, Ap + (long long)r * lda + k0 + c8);
        }
        __half* bd = Bs + buf * BSTG;
        if (BT) {
#pragma unroll
            for (int i = 0; i < 8; i++) {
                const int idx = t + i * 128;
                const int n = idx >> 3, c8 = (idx & 7) * 8;
                cp16(bd + n * BLD + c8, Bp + (long long)n * ldb + k0 + c8);
            }
        } else {
            // B: 64 rows x 128 cols = 1024 x 16B chunks
#pragma unroll
            for (int i = 0; i < 8; i++) {
                const int idx = t + i * 128;
                const int r = idx >> 4, c8 = (idx & 15) * 8;
                cp16(bd + r * BLD + c8, Bp + (long long)(k0 + r) * ldb + c8);
            }
        }
    };

    // ldmatrix per-lane address components
    const int a_lr = lane & 15;             // matrix row
    const int a_lk = (lane >> 4) << 3;      // k-half select
    const int bt_n = (lane & 7) + ((lane >> 4) & 1) * 8;   // BT: n within 16-group
    const int bt_k = ((lane >> 3) & 1) * 8;                // BT: k-half
    const int bn_k = (lane & 7) + ((lane >> 3) & 1) * 8;   // !BT: k row
    const int bn_n = ((lane >> 4) & 1) * 8;                // !BT: n-half

    // load all 8 B fragments for k-offset kk into bf
    auto load_bf = [&](uint32_t (&bf)[8][2], const __half* Bb, int kk) {
#pragma unroll
        for (int np = 0; np < 4; np++) {
            if (BT) {
                const __half* p = Bb + (wn + np * 16 + bt_n) * BLD + kk + bt_k;
                ldsm4(bf[np * 2][0], bf[np * 2][1], bf[np * 2 + 1][0], bf[np * 2 + 1][1],
                      (uint32_t)__cvta_generic_to_shared(p));
            } else {
                const __half* p = Bb + (kk + bn_k) * BLD + wn + np * 16 + bn_n;
                ldsm4t(bf[np * 2][0], bf[np * 2][1], bf[np * 2 + 1][0], bf[np * 2 + 1][1],
                       (uint32_t)__cvta_generic_to_shared(p));
            }
        }
    };

    const int ntiles = K / 64;              // >= 2 always here
    load_tiles(0, 0);  CP_COMMIT();
    load_tiles(64, 1); CP_COMMIT();

    uint32_t bfb[2][8][2];                  // B fragments, double-buffered across ksteps

    for (int it = 0; it < ntiles; ++it) {
        if (it + 1 < ntiles) { CP_WAIT(1); } else { CP_WAIT(0); }
        __syncthreads();

        const int buf = it % 3;
        const __half* Ab = As + buf * ASTG;
        const __half* Bb = Bs + buf * BSTG;

        load_bf(bfb[0], Bb, 0);             // kstep 0 B fragments
#pragma unroll
        for (int ks = 0; ks < 4; ks++) {
            const int kk = ks * 16;
            if (ks < 3) load_bf(bfb[(ks + 1) & 1], Bb, kk + 16);  // shadow under MMAs
            const uint32_t (&bf)[8][2] = bfb[ks & 1];
#pragma unroll
            for (int mt = 0; mt < 4; mt++) {
                uint32_t af[4];
                const __half* p = Ab + (wm + mt * 16 + a_lr) * ALD + kk + a_lk;
                ldsm4(af[0], af[1], af[2], af[3],
                      (uint32_t)__cvta_generic_to_shared(p));
#pragma unroll
                for (int nt = 0; nt < 8; nt++)
                    mma_f16(acc[mt][nt], af, bf[nt]);
            }
        }

        if (it + 2 < ntiles) {
            load_tiles((it + 2) * 64, (it + 2) % 3);
            CP_COMMIT();
        }
    }

    // ---- epilogue ----
#pragma unroll
    for (int mt = 0; mt < 4; mt++) {
#pragma unroll
        for (int nt = 0; nt < 8; nt++) {
            const int r   = bm + wm + mt * 16 + lr;
            const int col = bn + wn + nt * 8 + lc * 2;
            float v0 = acc[mt][nt][0], v1 = acc[mt][nt][1];
            float v2 = acc[mt][nt][2], v3 = acc[mt][nt][3];
            if (BIAS) {
                const float bi0 = bias[col], bi1 = bias[col + 1];
                v0 += bi0; v1 += bi1; v2 += bi0; v3 += bi1;
            }
            if (SCALE) { v0 *= scale; v1 *= scale; v2 *= scale; v3 *= scale; }
            if (HALFOUT) {
                __half2 h01 = __floats2half2_rn(v0, v1);
                __half2 h23 = __floats2half2_rn(v2, v3);
                *reinterpret_cast<__half2*>(&Ch[(long long)r * ldc + col])       = h01;
                *reinterpret_cast<__half2*>(&Ch[(long long)(r + 8) * ldc + col]) = h23;
            } else {
                *reinterpret_cast<float2*>(&Cp[(long long)r * ldc + col])       = make_float2(v0, v1);
                *reinterpret_cast<float2*>(&Cp[(long long)(r + 8) * ldc + col]) = make_float2(v2, v3);
            }
        }
    }
}

// Row softmax: fp16 scores in, fp16 probs out. One row per 256-thr block;
// one uint4 (8 halves) per thread. fp32 math in registers.
__global__ __launch_bounds__(256)
void softmax_h_kernel(const __half* __restrict__ S, __half* __restrict__ P)
{
    const long long row = blockIdx.x;
    const uint4* in = reinterpret_cast<const uint4*>(S + row * (long long)NN);
    uint4* outp     = reinterpret_cast<uint4*>(P + row * (long long)NN);
    const int t = threadIdx.x;

    uint4 v4 = in[t];
    __half2 h[4];
    h[0] = *reinterpret_cast<__half2*>(&v4.x);
    h[1] = *reinterpret_cast<__half2*>(&v4.y);
    h[2] = *reinterpret_cast<__half2*>(&v4.z);
    h[3] = *reinterpret_cast<__half2*>(&v4.w);

    float f[8];
#pragma unroll
    for (int i = 0; i < 4; i++) {
        float2 fv = __half22float2(h[i]);
        f[i * 2] = fv.x; f[i * 2 + 1] = fv.y;
    }

    float mx = -1e30f;
#pragma unroll
    for (int i = 0; i < 8; i++) mx = fmaxf(mx, f[i]);
#pragma unroll
    for (int o = 16; o > 0; o >>= 1)
        mx = fmaxf(mx, __shfl_xor_sync(0xFFFFFFFFu, mx, o));

    __shared__ float redm[8];
    __shared__ float reds[8];
    if ((t & 31) == 0) redm[t >> 5] = mx;
    __syncthreads();
#pragma unroll
    for (int i = 0; i < 8; i++) mx = fmaxf(mx, redm[i]);

    float s = 0.f;
#pragma unroll
    for (int i = 0; i < 8; i++) {
        f[i] = __expf(f[i] - mx);
        s += f[i];
    }
#pragma unroll
    for (int o = 16; o > 0; o >>= 1)
        s += __shfl_xor_sync(0xFFFFFFFFu, s, o);
    if ((t & 31) == 0) reds[t >> 5] = s;
    __syncthreads();
    s = 0.f;
#pragma unroll
    for (int i = 0; i < 8; i++) s += reds[i];

    const float inv = 1.f / s;
#pragma unroll
    for (int i = 0; i < 4; i++)
        h[i] = __floats2half2_rn(f[i * 2] * inv, f[i * 2 + 1] * inv);
    uint4 o4;
    o4.x = *reinterpret_cast<uint32_t*>(&h[0]);
    o4.y = *reinterpret_cast<uint32_t*>(&h[1]);
    o4.z = *reinterpret_cast<uint32_t*>(&h[2]);
    o4.w = *reinterpret_cast<uint32_t*>(&h[3]);
    outp[t] = o4;
}

// ---------------- host ----------------
extern "C" void kernel_launch(void* const* d_in, const int* in_sizes, int n_in,
                              void* d_out, int out_size)
{
    const float* x    = (const float*)d_in[0];   // [8, 2048, 768]
    const float* W    = (const float*)d_in[1];   // [768, 2304]
    const float* bias = (const float*)d_in[2];   // [2304]
    float* out        = (float*)d_out;           // [8, 2048, 768]

    __half *qkv, *sh, *ph, *xh, *wh;
    cudaGetSymbolAddress((void**)&qkv, g_qkv);
    cudaGetSymbolAddress((void**)&sh,  g_s);
    cudaGetSymbolAddress((void**)&ph,  g_p);
    cudaGetSymbolAddress((void**)&xh,  g_xh);
    cudaGetSymbolAddress((void**)&wh,  g_wh);

    // Dynamic smem (bytes): BT: 3*(128*72 + 128*72)*2 = 110592 ; !BT: 3*(128*72 + 64*136)*2 = 107520
    const int SM_BT = 3 * (128 * 72 + 128 * 72) * 2;
    const int SM_BN = 3 * (128 * 72 + 64 * 136) * 2;
    cudaFuncSetAttribute(gemm_f16_kernel<false, true,  false, true >,
                         cudaFuncAttributeMaxDynamicSharedMemorySize, SM_BN);
    cudaFuncSetAttribute(gemm_f16_kernel<true,  false, true,  true >,
                         cudaFuncAttributeMaxDynamicSharedMemorySize, SM_BT);
    cudaFuncSetAttribute(gemm_f16_kernel<false, false, false, false>,
                         cudaFuncAttributeMaxDynamicSharedMemorySize, SM_BN);

    const float scale = 0.03608439182435161f;    // 1/sqrt(768)

    // 0) x, W -> fp16
    {
        int n4x = (BB * NN * DD) / 4;
        int n4w = (DD * TRIPLE) / 4;
        cvt_f16_kernel<<<(n4x + 255) / 256, 256>>>((const float4*)x, (uint2*)xh, n4x);
        cvt_f16_kernel<<<(n4w + 255) / 256, 256>>>((const float4*)W, (uint2*)wh, n4w);
    }

    // 1) qkv = xh @ wh + b : M=16384, N=2304, K=768 -> fp16 out
    gemm_f16_kernel<false, true, false, true>
        <<<dim3(TRIPLE / 128, (BB * NN) / 128, 1), 128, SM_BN>>>(
        xh, DD, 0,
        wh, TRIPLE, 0,
        (float*)qkv, TRIPLE, 0,
        DD, bias, 1.f);

    // 2) S = Q @ K^T * scale : per batch M=2048, N=2048, K=768 -> fp16 scores
    gemm_f16_kernel<true, false, true, true>
        <<<dim3(NN / 128, NN / 128, BB), 128, SM_BT>>>(
        qkv,      TRIPLE, (long long)NN * TRIPLE,
        qkv + DD, TRIPLE, (long long)NN * TRIPLE,
        (float*)sh, NN,   (long long)NN * NN,
        DD, nullptr, scale);

    // 3) softmax rows (fp16 -> fp16)
    softmax_h_kernel<<<BB * NN, 256>>>(sh, ph);

    // 4) out = P @ V : per batch M=2048, N=768, K=2048 -> fp32 out
    gemm_f16_kernel<false, false, false, false>
        <<<dim3(DD / 128, NN / 128, BB), 128, SM_BN>>>(
        ph,           NN,     (long long)NN * NN,
        qkv + 2 * DD, TRIPLE, (long long)NN * TRIPLE,
        out,          DD,     (long long)NN * DD,
        NN, nullptr, 1.f);
}

// round 16
// speedup vs baseline: 2.5366x; 1.0817x over previous
#include <cuda_runtime.h>
#include <cuda_fp16.h>
#include <cstdint>

// Problem constants
#define BB 8
#define NN 2048
#define DD 768
#define TRIPLE 2304   // 3*768

// Scratch (device globals; no allocations anywhere)
__device__ __half g_qkv[(size_t)BB * NN * TRIPLE];  // 75 MB fp16 (q,k,v interleaved)
__device__ __half g_s[(size_t)BB * NN * NN];        // 67 MB fp16 scores
__device__ __half g_p[(size_t)BB * NN * NN];        // 67 MB fp16 softmax probs
__device__ __half g_xh[(size_t)BB * NN * DD];       // 25 MB x in fp16
__device__ __half g_wh[(size_t)DD * TRIPLE];        // 3.5 MB W in fp16

// ---------------- helpers ----------------
__device__ __forceinline__ void mma_f16(float c[4], const uint32_t a[4], const uint32_t b[2]) {
    asm volatile(
        "mma.sync.aligned.m16n8k16.row.col.f32.f16.f16.f32 "
        "{%0,%1,%2,%3}, {%4,%5,%6,%7}, {%8,%9}, {%0,%1,%2,%3};"
        : "+f"(c[0]), "+f"(c[1]), "+f"(c[2]), "+f"(c[3])
        : "r"(a[0]), "r"(a[1]), "r"(a[2]), "r"(a[3]), "r"(b[0]), "r"(b[1]));
}

__device__ __forceinline__ void ldsm4(uint32_t& r0, uint32_t& r1, uint32_t& r2, uint32_t& r3,
                                      uint32_t addr) {
    asm volatile("ldmatrix.sync.aligned.m8n8.x4.shared.b16 {%0,%1,%2,%3}, [%4];"
                 : "=r"(r0), "=r"(r1), "=r"(r2), "=r"(r3) : "r"(addr));
}
__device__ __forceinline__ void ldsm4t(uint32_t& r0, uint32_t& r1, uint32_t& r2, uint32_t& r3,
                                       uint32_t addr) {
    asm volatile("ldmatrix.sync.aligned.m8n8.x4.trans.shared.b16 {%0,%1,%2,%3}, [%4];"
                 : "=r"(r0), "=r"(r1), "=r"(r2), "=r"(r3) : "r"(addr));
}

__device__ __forceinline__ void cp16(const __half* dst_smem, const __half* src) {
    uint32_t d = (uint32_t)__cvta_generic_to_shared(dst_smem);
    asm volatile("cp.async.cg.shared.global [%0], [%1], 16;" :: "r"(d), "l"(src));
}
#define CP_COMMIT() asm volatile("cp.async.commit_group;")
#define CP_WAIT(n)  asm volatile("cp.async.wait_group %0;" :: "n"(n))

// fp32 -> fp16 conversion (vectorized)
__global__ void cvt_f16_kernel(const float4* __restrict__ in, uint2* __restrict__ out, int n4)
{
    int i = blockIdx.x * blockDim.x + threadIdx.x;
    if (i < n4) {
        float4 v = in[i];
        __half2 lo = __floats2half2_rn(v.x, v.y);
        __half2 hi = __floats2half2_rn(v.z, v.w);
        out[i] = make_uint2(*(uint32_t*)&lo, *(uint32_t*)&hi);
    }
}

// ---------------- FP16 tensor-core GEMM ----------------
//   C[M,N] = A[M,K](f16) * B(f16) (+bias) (*scale), accum fp32
//   BT=true : B row-major [N,K] (C = A*B^T); smem tile n-major [128][72]
//   BT=false: B row-major [K,N]; smem tile k-major [64][136], read via ldmatrix.trans
// CTA tile 128x128, BK=64, 128 thr = 4 warps of 64x64 (2x2), 2 CTAs/SM, 3-stage.
// Single-barrier mainloop + interleaved cp.async issue: the 16 LDGSTS/warp for
// tile it+2 are issued in 4 slivers, one after each kstep's MMA block, so the
// LSU burst is shadowed by queued tensor work instead of exposed at tile end.
template<bool BT, bool BIAS, bool SCALE, bool HALFOUT>
__global__ __launch_bounds__(128, 2)
void gemm_f16_kernel(const __half* __restrict__ A, int lda, long long sA,
                     const __half* __restrict__ B, int ldb, long long sB,
                     float* __restrict__ Cf, int ldc, long long sC,
                     int K, const float* __restrict__ bias, float scale)
{
    constexpr int ALD   = 72;                 // 144B row stride = 9x16B (odd) -> conflict-free
    constexpr int BROWS = BT ? 128 : 64;
    constexpr int BLD   = BT ? 72 : 136;      // 272B = 17x16B (odd)
    constexpr int ASTG  = 128 * ALD;
    constexpr int BSTG  = BROWS * BLD;

    extern __shared__ __half sm[];
    __half* As = sm;                          // [3][128][72]
    __half* Bs = sm + 3 * ASTG;               // [3][BROWS][BLD]

    const int t  = threadIdx.x;
    const int bm = blockIdx.y * 128;
    const int bn = blockIdx.x * 128;
    const __half* Ap = A + (long long)blockIdx.z * sA + (long long)bm * lda;
    const __half* Bp = B + (long long)blockIdx.z * sB
                         + (BT ? (long long)bn * ldb : (long long)bn);
    float*  Cp = Cf + (long long)blockIdx.z * sC;
    __half* Ch = reinterpret_cast<__half*>(Cf) + (long long)blockIdx.z * sC;

    const int warp = t >> 5, lane = t & 31;
    const int wm = (warp & 1) * 64;           // 2 warp rows
    const int wn = (warp >> 1) * 64;          // 2 warp cols
    const int lr = lane >> 2, lc = lane & 3;

    float acc[4][8][4];
#pragma unroll
    for (int i = 0; i < 4; i++)
#pragma unroll
        for (int j = 0; j < 8; j++)
#pragma unroll
            for (int r = 0; r < 4; r++) acc[i][j][r] = 0.f;

    // Issue 1/4 of a tile's cp.asyncs: A-loop iters {2p,2p+1}, B-loop iters {2p,2p+1}.
    auto load_part = [&](int k0, int buf, int p) {
        __half* ad = As + buf * ASTG;
#pragma unroll
        for (int i = 0; i < 2; i++) {
            const int idx = t + (2 * p + i) * 128;     // A: 1024 x 16B chunks
            const int r = idx >> 3, c8 = (idx & 7) * 8;
            cp16(ad + r * ALD + c8, Ap + (long long)r * lda + k0 + c8);
        }
        __half* bd = Bs + buf * BSTG;
        if (BT) {
#pragma unroll
            for (int i = 0; i < 2; i++) {
                const int idx = t + (2 * p + i) * 128;
                const int n = idx >> 3, c8 = (idx & 7) * 8;
                cp16(bd + n * BLD + c8, Bp + (long long)n * ldb + k0 + c8);
            }
        } else {
#pragma unroll
            for (int i = 0; i < 2; i++) {
                const int idx = t + (2 * p + i) * 128;
                const int r = idx >> 4, c8 = (idx & 15) * 8;
                cp16(bd + r * BLD + c8, Bp + (long long)(k0 + r) * ldb + c8);
            }
        }
    };

    auto load_tiles = [&](int k0, int buf) {
#pragma unroll
        for (int p = 0; p < 4; p++) load_part(k0, buf, p);
    };

    // ldmatrix per-lane address components
    const int a_lr = lane & 15;             // matrix row
    const int a_lk = (lane >> 4) << 3;      // k-half select
    const int bt_n = (lane & 7) + ((lane >> 4) & 1) * 8;   // BT: n within 16-group
    const int bt_k = ((lane >> 3) & 1) * 8;                // BT: k-half
    const int bn_k = (lane & 7) + ((lane >> 3) & 1) * 8;   // !BT: k row
    const int bn_n = ((lane >> 4) & 1) * 8;                // !BT: n-half

    // load all 8 B fragments for k-offset kk into bf
    auto load_bf = [&](uint32_t (&bf)[8][2], const __half* Bb, int kk) {
#pragma unroll
        for (int np = 0; np < 4; np++) {
            if (BT) {
                const __half* p = Bb + (wn + np * 16 + bt_n) * BLD + kk + bt_k;
                ldsm4(bf[np * 2][0], bf[np * 2][1], bf[np * 2 + 1][0], bf[np * 2 + 1][1],
                      (uint32_t)__cvta_generic_to_shared(p));
            } else {
                const __half* p = Bb + (kk + bn_k) * BLD + wn + np * 16 + bn_n;
                ldsm4t(bf[np * 2][0], bf[np * 2][1], bf[np * 2 + 1][0], bf[np * 2 + 1][1],
                       (uint32_t)__cvta_generic_to_shared(p));
            }
        }
    };

    const int ntiles = K / 64;              // >= 2 always here
    load_tiles(0, 0);  CP_COMMIT();
    load_tiles(64, 1); CP_COMMIT();

    uint32_t bfb[2][8][2];                  // B fragments, double-buffered across ksteps

    for (int it = 0; it < ntiles; ++it) {
        if (it + 1 < ntiles) { CP_WAIT(1); } else { CP_WAIT(0); }
        __syncthreads();

        const int buf = it % 3;
        const __half* Ab = As + buf * ASTG;
        const __half* Bb = Bs + buf * BSTG;
        const bool prefetch = (it + 2 < ntiles);
        const int pk0  = (it + 2) * 64;
        const int pbuf = (it + 2) % 3;

        load_bf(bfb[0], Bb, 0);             // kstep 0 B fragments
#pragma unroll
        for (int ks = 0; ks < 4; ks++) {
            const int kk = ks * 16;
            if (ks < 3) load_bf(bfb[(ks + 1) & 1], Bb, kk + 16);  // shadow under MMAs
            const uint32_t (&bf)[8][2] = bfb[ks & 1];
#pragma unroll
            for (int mt = 0; mt < 4; mt++) {
                uint32_t af[4];
                const __half* p = Ab + (wm + mt * 16 + a_lr) * ALD + kk + a_lk;
                ldsm4(af[0], af[1], af[2], af[3],
                      (uint32_t)__cvta_generic_to_shared(p));
#pragma unroll
                for (int nt = 0; nt < 8; nt++)
                    mma_f16(acc[mt][nt], af, bf[nt]);
            }
            if (prefetch) load_part(pk0, pbuf, ks);   // sliver of tile it+2
        }

        if (prefetch) CP_COMMIT();
    }

    // ---- epilogue ----
#pragma unroll
    for (int mt = 0; mt < 4; mt++) {
#pragma unroll
        for (int nt = 0; nt < 8; nt++) {
            const int r   = bm + wm + mt * 16 + lr;
            const int col = bn + wn + nt * 8 + lc * 2;
            float v0 = acc[mt][nt][0], v1 = acc[mt][nt][1];
            float v2 = acc[mt][nt][2], v3 = acc[mt][nt][3];
            if (BIAS) {
                const float bi0 = bias[col], bi1 = bias[col + 1];
                v0 += bi0; v1 += bi1; v2 += bi0; v3 += bi1;
            }
            if (SCALE) { v0 *= scale; v1 *= scale; v2 *= scale; v3 *= scale; }
            if (HALFOUT) {
                __half2 h01 = __floats2half2_rn(v0, v1);
                __half2 h23 = __floats2half2_rn(v2, v3);
                *reinterpret_cast<__half2*>(&Ch[(long long)r * ldc + col])       = h01;
                *reinterpret_cast<__half2*>(&Ch[(long long)(r + 8) * ldc + col]) = h23;
            } else {
                *reinterpret_cast<float2*>(&Cp[(long long)r * ldc + col])       = make_float2(v0, v1);
                *reinterpret_cast<float2*>(&Cp[(long long)(r + 8) * ldc + col]) = make_float2(v2, v3);
            }
        }
    }
}

// Row softmax: fp16 scores in, fp16 probs out. One row per 256-thr block;
// one uint4 (8 halves) per thread. fp32 math in registers.
__global__ __launch_bounds__(256)
void softmax_h_kernel(const __half* __restrict__ S, __half* __restrict__ P)
{
    const long long row = blockIdx.x;
    const uint4* in = reinterpret_cast<const uint4*>(S + row * (long long)NN);
    uint4* outp     = reinterpret_cast<uint4*>(P + row * (long long)NN);
    const int t = threadIdx.x;

    uint4 v4 = in[t];
    __half2 h[4];
    h[0] = *reinterpret_cast<__half2*>(&v4.x);
    h[1] = *reinterpret_cast<__half2*>(&v4.y);
    h[2] = *reinterpret_cast<__half2*>(&v4.z);
    h[3] = *reinterpret_cast<__half2*>(&v4.w);

    float f[8];
#pragma unroll
    for (int i = 0; i < 4; i++) {
        float2 fv = __half22float2(h[i]);
        f[i * 2] = fv.x; f[i * 2 + 1] = fv.y;
    }

    float mx = -1e30f;
#pragma unroll
    for (int i = 0; i < 8; i++) mx = fmaxf(mx, f[i]);
#pragma unroll
    for (int o = 16; o > 0; o >>= 1)
        mx = fmaxf(mx, __shfl_xor_sync(0xFFFFFFFFu, mx, o));

    __shared__ float redm[8];
    __shared__ float reds[8];
    if ((t & 31) == 0) redm[t >> 5] = mx;
    __syncthreads();
#pragma unroll
    for (int i = 0; i < 8; i++) mx = fmaxf(mx, redm[i]);

    float s = 0.f;
#pragma unroll
    for (int i = 0; i < 8; i++) {
        f[i] = __expf(f[i] - mx);
        s += f[i];
    }
#pragma unroll
    for (int o = 16; o > 0; o >>= 1)
        s += __shfl_xor_sync(0xFFFFFFFFu, s, o);
    if ((t & 31) == 0) reds[t >> 5] = s;
    __syncthreads();
    s = 0.f;
#pragma unroll
    for (int i = 0; i < 8; i++) s += reds[i];

    const float inv = 1.f / s;
#pragma unroll
    for (int i = 0; i < 4; i++)
        h[i] = __floats2half2_rn(f[i * 2] * inv, f[i * 2 + 1] * inv);
    uint4 o4;
    o4.x = *reinterpret_cast<uint32_t*>(&h[0]);
    o4.y = *reinterpret_cast<uint32_t*>(&h[1]);
    o4.z = *reinterpret_cast<uint32_t*>(&h[2]);
    o4.w = *reinterpret_cast<uint32_t*>(&h[3]);
    outp[t] = o4;
}

// ---------------- host ----------------
extern "C" void kernel_launch(void* const* d_in, const int* in_sizes, int n_in,
                              void* d_out, int out_size)
{
    const float* x    = (const float*)d_in[0];   // [8, 2048, 768]
    const float* W    = (const float*)d_in[1];   // [768, 2304]
    const float* bias = (const float*)d_in[2];   // [2304]
    float* out        = (float*)d_out;           // [8, 2048, 768]

    __half *qkv, *sh, *ph, *xh, *wh;
    cudaGetSymbolAddress((void**)&qkv, g_qkv);
    cudaGetSymbolAddress((void**)&sh,  g_s);
    cudaGetSymbolAddress((void**)&ph,  g_p);
    cudaGetSymbolAddress((void**)&xh,  g_xh);
    cudaGetSymbolAddress((void**)&wh,  g_wh);

    // Dynamic smem (bytes): BT: 3*(128*72 + 128*72)*2 = 110592 ; !BT: 3*(128*72 + 64*136)*2 = 107520
    const int SM_BT = 3 * (128 * 72 + 128 * 72) * 2;
    const int SM_BN = 3 * (128 * 72 + 64 * 136) * 2;
    cudaFuncSetAttribute(gemm_f16_kernel<false, true,  false, true >,
                         cudaFuncAttributeMaxDynamicSharedMemorySize, SM_BN);
    cudaFuncSetAttribute(gemm_f16_kernel<true,  false, true,  true >,
                         cudaFuncAttributeMaxDynamicSharedMemorySize, SM_BT);
    cudaFuncSetAttribute(gemm_f16_kernel<false, false, false, false>,
                         cudaFuncAttributeMaxDynamicSharedMemorySize, SM_BN);

    const float scale = 0.03608439182435161f;    // 1/sqrt(768)

    // 0) x, W -> fp16
    {
        int n4x = (BB * NN * DD) / 4;
        int n4w = (DD * TRIPLE) / 4;
        cvt_f16_kernel<<<(n4x + 255) / 256, 256>>>((const float4*)x, (uint2*)xh, n4x);
        cvt_f16_kernel<<<(n4w + 255) / 256, 256>>>((const float4*)W, (uint2*)wh, n4w);
    }

    // 1) qkv = xh @ wh + b : M=16384, N=2304, K=768 -> fp16 out
    gemm_f16_kernel<false, true, false, true>
        <<<dim3(TRIPLE / 128, (BB * NN) / 128, 1), 128, SM_BN>>>(
        xh, DD, 0,
        wh, TRIPLE, 0,
        (float*)qkv, TRIPLE, 0,
        DD, bias, 1.f);

    // 2) S = Q @ K^T * scale : per batch M=2048, N=2048, K=768 -> fp16 scores
    gemm_f16_kernel<true, false, true, true>
        <<<dim3(NN / 128, NN / 128, BB), 128, SM_BT>>>(
        qkv,      TRIPLE, (long long)NN * TRIPLE,
        qkv + DD, TRIPLE, (long long)NN * TRIPLE,
        (float*)sh, NN,   (long long)NN * NN,
        DD, nullptr, scale);

    // 3) softmax rows (fp16 -> fp16)
    softmax_h_kernel<<<BB * NN, 256>>>(sh, ph);

    // 4) out = P @ V : per batch M=2048, N=768, K=2048 -> fp32 out
    gemm_f16_kernel<false, false, false, false>
        <<<dim3(DD / 128, NN / 128, BB), 128, SM_BN>>>(
        ph,           NN,     (long long)NN * NN,
        qkv + 2 * DD, TRIPLE, (long long)NN * TRIPLE,
        out,          DD,     (long long)NN * DD,
        NN, nullptr, 1.f);
}